// round 8
// baseline (speedup 1.0000x reference)
#include <cuda_runtime.h>
#include <cstdint>
#include <cstddef>

// ---------------- problem constants ----------------
#define NN     50000
#define NE     500000
#define DNODE  64
#define DEDGE  8
#define DIN    72
#define HMSG   128
#define DMSG   64
#define HUPD   64
#define DOUT   32
#define HTEN   32

typedef unsigned long long ull;

// ---------------- device scratch ----------------
__device__ float g_aggr[(size_t)NN * DMSG];
__device__ float g_cnt[NN];
__device__ int   g_idx64;

// ---------------- packed f32x2 helpers ----------------
__device__ __forceinline__ ull fma2(ull a, ull b, ull c) {
    ull d; asm("fma.rn.f32x2 %0, %1, %2, %3;" : "=l"(d) : "l"(a), "l"(b), "l"(c));
    return d;
}
__device__ __forceinline__ ull dup2(float x) {
    ull d; asm("mov.b64 %0, {%1, %1};" : "=l"(d) : "f"(x)); return d;
}
__device__ __forceinline__ ull pack2(float x, float y) {
    ull d; asm("mov.b64 %0, {%1, %2};" : "=l"(d) : "f"(x), "f"(y)); return d;
}
__device__ __forceinline__ float2 unpack2(ull v) {
    float2 r; asm("mov.b64 {%0, %1}, %2;" : "=f"(r.x), "=f"(r.y) : "l"(v)); return r;
}
__device__ __forceinline__ void red_add_v2(float* addr, float a, float b) {
    asm volatile("red.global.add.v2.f32 [%0], {%1, %2};"
                 :: "l"(addr), "f"(a), "f"(b) : "memory");
}
__device__ __forceinline__ void red_add_f32(float* addr, float v) {
    asm volatile("red.global.add.f32 [%0], %1;"
                 :: "l"(addr), "f"(v) : "memory");
}

// ---------------- init ----------------
__global__ void init_kernel(const void* __restrict__ ei) {
    size_t tid    = (size_t)blockIdx.x * blockDim.x + threadIdx.x;
    size_t stride = (size_t)gridDim.x * blockDim.x;
    for (size_t i = tid; i < (size_t)NN * DMSG; i += stride) g_aggr[i] = 0.f;
    for (size_t i = tid; i < (size_t)NN; i += stride)        g_cnt[i]  = 0.f;
    if (tid == 0) {
        const unsigned long long* p = (const unsigned long long*)ei;
        int is64 = 1;
        for (int k = 0; k < 64; k++)
            if (p[k] >= (unsigned long long)NN) { is64 = 0; break; }
        g_idx64 = is64;
    }
}

// ---------------- edge kernel ----------------
#define EK_NW 16
#define EK_B  4

#define OFF_WM1 0
#define OFF_WM2 (OFF_WM1 + DIN*HMSG)            // 9216
#define OFF_WT1 (OFF_WM2 + HMSG*DMSG)           // 17408
#define OFF_BM1 (OFF_WT1 + DMSG*HTEN)           // 19456
#define OFF_BM2 (OFF_BM1 + HMSG)                // 19584
#define OFF_BT1 (OFF_BM2 + DMSG)                // 19648
#define OFF_WT2 (OFF_BT1 + HTEN)                // 19680
#define OFF_BT2 (OFF_WT2 + HTEN)                // 19712
#define OFF_IN  (OFF_BT2 + 4)                   // 19716 (16B-aligned in bytes)
#define OFF_H   (OFF_IN + EK_NW*EK_B*2*DIN)     // 28932
#define OFF_MS  (OFF_H + EK_NW*EK_B*2*HMSG)     // 45316
#define EK_SMEM_FLOATS (OFF_MS + EK_NW*EK_B*DMSG)  // 49412 -> 197648 B

__global__ void __launch_bounds__(EK_NW * 32, 1)
edge_kernel(const float* __restrict__ x, const void* __restrict__ ei,
            const float* __restrict__ ea,
            const float* __restrict__ Wm1, const float* __restrict__ bm1,
            const float* __restrict__ Wm2, const float* __restrict__ bm2,
            const float* __restrict__ Wt1, const float* __restrict__ bt1,
            const float* __restrict__ Wt2, const float* __restrict__ bt2,
            float* __restrict__ e_out)
{
    extern __shared__ float sm[];
    for (int i = threadIdx.x; i < DIN*HMSG;  i += blockDim.x) sm[OFF_WM1+i] = Wm1[i];
    for (int i = threadIdx.x; i < HMSG*DMSG; i += blockDim.x) sm[OFF_WM2+i] = Wm2[i];
    for (int i = threadIdx.x; i < DMSG*HTEN; i += blockDim.x) sm[OFF_WT1+i] = Wt1[i];
    for (int i = threadIdx.x; i < HMSG; i += blockDim.x) sm[OFF_BM1+i] = bm1[i];
    for (int i = threadIdx.x; i < DMSG; i += blockDim.x) sm[OFF_BM2+i] = bm2[i];
    for (int i = threadIdx.x; i < HTEN; i += blockDim.x) {
        sm[OFF_BT1+i] = bt1[i];
        sm[OFF_WT2+i] = Wt2[i];
    }
    if (threadIdx.x == 0) sm[OFF_BT2] = bt2[0];
    __syncthreads();

    const int lane = threadIdx.x & 31;
    const int warp = threadIdx.x >> 5;
    const int half = lane >> 4;
    const int l16  = lane & 15;

    float* in_w = sm + OFF_IN + warp * (EK_B * 2 * DIN);    // duplicated inputs
    float* h_w  = sm + OFF_H  + warp * (EK_B * 2 * HMSG);   // {fwd,bwd} interleaved
    float* ms_w = sm + OFF_MS + warp * (EK_B * DMSG);       // symmetrized messages

    // loop-invariant per-lane parameters in registers
    const float4 b1p  = *(const float4*)(sm + OFF_BM1 + 4*lane);   // L1 bias, outputs 4L..4L+3
    const float4 b2p  = *(const float4*)(sm + OFF_BM2 + 4*l16);    // L2 bias, outputs 4*l16..
    const float2 bt1p = *(const float2*)(sm + OFF_BT1 + 2*l16);
    const float2 wt2p = *(const float2*)(sm + OFF_WT2 + 2*l16);
    const float  bt2v = sm[OFF_BT2];

    const bool idx64 = (g_idx64 != 0);
    const long long* ei64 = (const long long*)ei;
    const int*       ei32 = (const int*)ei;

    const int gw     = blockIdx.x * EK_NW + warp;
    const int nwarps = gridDim.x * EK_NW;

    for (int base = gw * EK_B; base < NE; base += nwarps * EK_B) {
        int sr[EK_B], tg[EK_B];
        #pragma unroll
        for (int e = 0; e < EK_B; e++) {
            int id = base + e;
            if (idx64) { sr[e] = (int)ei64[id]; tg[e] = (int)ei64[NE + id]; }
            else       { sr[e] = ei32[id];      tg[e] = ei32[NE + id]; }
        }

        // ---- stage duplicated input [v0,v0,v1,v1,...] per edge ----
        #pragma unroll
        for (int e = 0; e < EK_B; e++) {
            const float2 xt = *(const float2*)(x + (size_t)tg[e]*DNODE + 2*lane);
            const float2 xs = *(const float2*)(x + (size_t)sr[e]*DNODE + 2*lane);
            float4 d;
            d.x = xt.x - xs.x; d.y = d.x;
            d.z = xt.y - xs.y; d.w = d.z;
            *(float4*)(in_w + e*(2*DIN) + 4*lane) = d;
        }
        if (lane < 4*EK_B) {
            int e = lane >> 2, l4 = lane & 3;
            float2 ev = *(const float2*)(ea + (size_t)(base + e)*DEDGE + 2*l4);
            float4 d; d.x = ev.x; d.y = ev.x; d.z = ev.y; d.w = ev.y;
            *(float4*)(in_w + e*(2*DIN) + 2*DNODE + 4*l4) = d;
        }
        __syncwarp();

        // ---- layer 1: z = W1^T.in (forward linear part only) ----
        // lane owns outputs 4L..4L+3; fwd = relu(z+b), bwd = relu(b-z)
        ull z[EK_B][2];
        #pragma unroll
        for (int e = 0; e < EK_B; e++) { z[e][0] = 0ULL; z[e][1] = 0ULL; }

        #pragma unroll 8
        for (int i = 0; i < DIN; i++) {
            float4 w4 = *(const float4*)(sm + OFF_WM1 + i*HMSG + 4*lane);
            ull wa = pack2(w4.x, w4.y);
            ull wb = pack2(w4.z, w4.w);
            #pragma unroll
            for (int e = 0; e < EK_B; e++) {
                ull vv = *(const ull*)(in_w + e*(2*DIN) + 2*i);
                z[e][0] = fma2(vv, wa, z[e][0]);
                z[e][1] = fma2(vv, wb, z[e][1]);
            }
        }
        #pragma unroll
        for (int e = 0; e < EK_B; e++) {
            float2 za = unpack2(z[e][0]);
            float2 zb = unpack2(z[e][1]);
            float4 h0, h1;
            h0.x = fmaxf(za.x + b1p.x, 0.f); h0.y = fmaxf(b1p.x - za.x, 0.f);
            h0.z = fmaxf(za.y + b1p.y, 0.f); h0.w = fmaxf(b1p.y - za.y, 0.f);
            h1.x = fmaxf(zb.x + b1p.z, 0.f); h1.y = fmaxf(b1p.z - zb.x, 0.f);
            h1.z = fmaxf(zb.y + b1p.w, 0.f); h1.w = fmaxf(b1p.w - zb.y, 0.f);
            *(float4*)(h_w + e*(2*HMSG) + 8*lane)     = h0;  // j=4L,4L+1 as {f,b}
            *(float4*)(h_w + e*(2*HMSG) + 8*lane + 4) = h1;  // j=4L+2,4L+3
        }
        __syncwarp();

        // ---- layer 2: half-warp per edge; acc = {m_fwd_o, m_bwd_o} ----
        // lanes 0-15: edges 0 & 2; lanes 16-31: edges 1 & 3. Outputs 4*l16..+3.
        ull acc[2][4];
        #pragma unroll
        for (int k = 0; k < 4; k++) { acc[0][k] = 0ULL; acc[1][k] = 0ULL; }

        const float* hA = h_w + half*(2*HMSG);
        const float* hB = h_w + (2 + half)*(2*HMSG);
        #pragma unroll 4
        for (int j = 0; j < HMSG; j++) {
            float4 w4 = *(const float4*)(sm + OFF_WM2 + j*DMSG + 4*l16);
            ull hvA = *(const ull*)(hA + 2*j);
            ull hvB = *(const ull*)(hB + 2*j);
            ull d0 = dup2(w4.x), d1 = dup2(w4.y), d2 = dup2(w4.z), d3 = dup2(w4.w);
            acc[0][0] = fma2(hvA, d0, acc[0][0]);
            acc[0][1] = fma2(hvA, d1, acc[0][1]);
            acc[0][2] = fma2(hvA, d2, acc[0][2]);
            acc[0][3] = fma2(hvA, d3, acc[0][3]);
            acc[1][0] = fma2(hvB, d0, acc[1][0]);
            acc[1][1] = fma2(hvB, d1, acc[1][1]);
            acc[1][2] = fma2(hvB, d2, acc[1][2]);
            acc[1][3] = fma2(hvB, d3, acc[1][3]);
        }

        #pragma unroll
        for (int es = 0; es < 2; es++) {
            const int e = es*2 + half;
            const int t = half ? tg[es*2+1] : tg[es*2];
            const int s = half ? sr[es*2+1] : sr[es*2];
            float2 a0 = unpack2(acc[es][0]);
            float2 a1 = unpack2(acc[es][1]);
            float2 a2 = unpack2(acc[es][2]);
            float2 a3 = unpack2(acc[es][3]);
            float f0 = fmaxf(a0.x + b2p.x, 0.f), g0 = fmaxf(a0.y + b2p.x, 0.f);
            float f1 = fmaxf(a1.x + b2p.y, 0.f), g1 = fmaxf(a1.y + b2p.y, 0.f);
            float f2 = fmaxf(a2.x + b2p.z, 0.f), g2 = fmaxf(a2.y + b2p.z, 0.f);
            float f3 = fmaxf(a3.x + b2p.w, 0.f), g3 = fmaxf(a3.y + b2p.w, 0.f);
            red_add_v2(g_aggr + (size_t)t*DMSG + 4*l16,     f0, f1);
            red_add_v2(g_aggr + (size_t)t*DMSG + 4*l16 + 2, f2, f3);
            red_add_v2(g_aggr + (size_t)s*DMSG + 4*l16,     g0, g1);
            red_add_v2(g_aggr + (size_t)s*DMSG + 4*l16 + 2, g2, g3);
            float4 sv; sv.x = f0+g0; sv.y = f1+g1; sv.z = f2+g2; sv.w = f3+g3;
            *(float4*)(ms_w + e*DMSG + 4*l16) = sv;
        }
        if (lane == 0) {
            #pragma unroll
            for (int e = 0; e < EK_B; e++) {
                red_add_f32(g_cnt + tg[e], 1.f);
                red_add_f32(g_cnt + sr[e], 1.f);
            }
        }
        __syncwarp();

        // ---- tension MLP: half-warp per edge, f32x2 over d-pairs ----
        #pragma unroll
        for (int p = 0; p < 2; p++) {
            const int e = p*2 + half;
            const float* msp = ms_w + e*DMSG;
            ull accP = 0ULL;                 // {out 2*l16, out 2*l16+1}
            #pragma unroll 8
            for (int d = 0; d < DMSG; d++) {
                ull wv  = *(const ull*)(sm + OFF_WT1 + d*HTEN + 2*l16);
                ull svd = dup2(msp[d]);
                accP = fma2(svd, wv, accP);
            }
            float2 ac = unpack2(accP);
            float h0 = fmaxf(ac.x + bt1p.x, 0.f);
            float h1 = fmaxf(ac.y + bt1p.y, 0.f);
            float c  = h0*wt2p.x + h1*wt2p.y;
            #pragma unroll
            for (int off = 8; off > 0; off >>= 1)
                c += __shfl_xor_sync(0xffffffffu, c, off);
            if (l16 == 0) e_out[base + e] = c + bt2v;
        }
        __syncwarp();
    }
}

// ---------------- node kernel ----------------
#define NK_NW 16
#define NOFF_WU1 0
#define NOFF_WU2 (NOFF_WU1 + (DNODE+DMSG)*HUPD)
#define NOFF_BU1 (NOFF_WU2 + HUPD*DOUT)
#define NOFF_BU2 (NOFF_BU1 + HUPD)
#define NOFF_IN  (NOFF_BU2 + DOUT)
#define NOFF_H   (NOFF_IN + NK_NW*(DNODE+DMSG))
#define NK_SMEM_FLOATS (NOFF_H + NK_NW*HUPD)

__global__ void __launch_bounds__(NK_NW * 32, 1)
node_kernel(const float* __restrict__ x,
            const float* __restrict__ Wu1, const float* __restrict__ bu1,
            const float* __restrict__ Wu2, const float* __restrict__ bu2,
            float* __restrict__ x_out)
{
    extern __shared__ float sm[];
    for (int i = threadIdx.x; i < (DNODE+DMSG)*HUPD; i += blockDim.x) sm[NOFF_WU1+i] = Wu1[i];
    for (int i = threadIdx.x; i < HUPD*DOUT;          i += blockDim.x) sm[NOFF_WU2+i] = Wu2[i];
    for (int i = threadIdx.x; i < HUPD; i += blockDim.x) sm[NOFF_BU1+i] = bu1[i];
    for (int i = threadIdx.x; i < DOUT; i += blockDim.x) sm[NOFF_BU2+i] = bu2[i];
    __syncthreads();

    const int lane = threadIdx.x & 31;
    const int warp = threadIdx.x >> 5;
    float* in_sh = sm + NOFF_IN + warp * (DNODE + DMSG);
    float* h_sh  = sm + NOFF_H  + warp * HUPD;
    const int gw     = blockIdx.x * NK_NW + warp;
    const int nwarps = gridDim.x * NK_NW;

    for (int n = gw; n < NN; n += nwarps) {
        float inv = 1.f / fmaxf(g_cnt[n], 1.f);
        in_sh[lane]      = x[(size_t)n*DNODE + lane];
        in_sh[32 + lane] = x[(size_t)n*DNODE + 32 + lane];
        in_sh[64 + lane] = g_aggr[(size_t)n*DMSG + lane] * inv;
        in_sh[96 + lane] = g_aggr[(size_t)n*DMSG + 32 + lane] * inv;
        __syncwarp();

        float a0 = 0.f, a1 = 0.f;
        #pragma unroll 8
        for (int i = 0; i < DNODE + DMSG; i += 2) {
            float2 v = *(const float2*)&in_sh[i];
            a0 = fmaf(v.x, sm[NOFF_WU1 + i*HUPD         + lane], a0);
            a0 = fmaf(v.y, sm[NOFF_WU1 + (i+1)*HUPD     + lane], a0);
            a1 = fmaf(v.x, sm[NOFF_WU1 + i*HUPD    + 32 + lane], a1);
            a1 = fmaf(v.y, sm[NOFF_WU1 + (i+1)*HUPD + 32 + lane], a1);
        }
        h_sh[lane]      = fmaxf(a0 + sm[NOFF_BU1 + lane], 0.f);
        h_sh[32 + lane] = fmaxf(a1 + sm[NOFF_BU1 + 32 + lane], 0.f);
        __syncwarp();

        float o = 0.f;
        #pragma unroll 8
        for (int j = 0; j < HUPD; j += 2) {
            float2 v = *(const float2*)&h_sh[j];
            o = fmaf(v.x, sm[NOFF_WU2 + j*DOUT     + lane], o);
            o = fmaf(v.y, sm[NOFF_WU2 + (j+1)*DOUT + lane], o);
        }
        x_out[(size_t)n*DOUT + lane] = o + sm[NOFF_BU2 + lane];
        __syncwarp();
    }
}

// ---------------- launch ----------------
extern "C" void kernel_launch(void* const* d_in, const int* in_sizes, int n_in,
                              void* d_out, int out_size)
{
    (void)in_sizes; (void)n_in; (void)out_size;
    const float* x   = (const float*)d_in[0];
    const void*  ei  =               d_in[1];
    const float* ea  = (const float*)d_in[2];
    const float* Wm1 = (const float*)d_in[3];
    const float* bm1 = (const float*)d_in[4];
    const float* Wm2 = (const float*)d_in[5];
    const float* bm2 = (const float*)d_in[6];
    const float* Wu1 = (const float*)d_in[7];
    const float* bu1 = (const float*)d_in[8];
    const float* Wu2 = (const float*)d_in[9];
    const float* bu2 = (const float*)d_in[10];
    const float* Wt1 = (const float*)d_in[11];
    const float* bt1 = (const float*)d_in[12];
    const float* Wt2 = (const float*)d_in[13];
    const float* bt2 = (const float*)d_in[14];

    float* x_out = (float*)d_out;
    float* e_out = x_out + (size_t)NN * DOUT;

    int nsm = 148;
    cudaDeviceGetAttribute(&nsm, cudaDevAttrMultiProcessorCount, 0);

    cudaFuncSetAttribute(edge_kernel, cudaFuncAttributeMaxDynamicSharedMemorySize,
                         EK_SMEM_FLOATS * (int)sizeof(float));
    cudaFuncSetAttribute(node_kernel, cudaFuncAttributeMaxDynamicSharedMemorySize,
                         NK_SMEM_FLOATS * (int)sizeof(float));

    init_kernel<<<1024, 256>>>(ei);
    edge_kernel<<<nsm, EK_NW * 32, EK_SMEM_FLOATS * sizeof(float)>>>(
        x, ei, ea, Wm1, bm1, Wm2, bm2, Wt1, bt1, Wt2, bt2, e_out);
    node_kernel<<<nsm, NK_NW * 32, NK_SMEM_FLOATS * sizeof(float)>>>(
        x, Wu1, bu1, Wu2, bu2, x_out);
}

// round 9
// speedup vs baseline: 1.0094x; 1.0094x over previous
#include <cuda_runtime.h>
#include <cstdint>
#include <cstddef>

// ---------------- problem constants ----------------
#define NN     50000
#define NE     500000
#define DNODE  64
#define DEDGE  8
#define DIN    72
#define HMSG   128
#define DMSG   64
#define HUPD   64
#define DOUT   32
#define HTEN   32

typedef unsigned long long ull;

// ---------------- device scratch ----------------
__device__ float g_aggr[(size_t)NN * DMSG];
__device__ float g_cnt[NN];
__device__ int   g_idx64;

// ---------------- packed f32x2 helpers ----------------
__device__ __forceinline__ ull fma2(ull a, ull b, ull c) {
    ull d; asm("fma.rn.f32x2 %0, %1, %2, %3;" : "=l"(d) : "l"(a), "l"(b), "l"(c));
    return d;
}
__device__ __forceinline__ ull dup2(float x) {
    ull d; asm("mov.b64 %0, {%1, %1};" : "=l"(d) : "f"(x)); return d;
}
__device__ __forceinline__ float2 unpack2(ull v) {
    float2 r; asm("mov.b64 {%0, %1}, %2;" : "=f"(r.x), "=f"(r.y) : "l"(v)); return r;
}
__device__ __forceinline__ void red_add_v2(float* addr, float a, float b) {
    asm volatile("red.global.add.v2.f32 [%0], {%1, %2};"
                 :: "l"(addr), "f"(a), "f"(b) : "memory");
}
__device__ __forceinline__ void red_add_f32(float* addr, float v) {
    asm volatile("red.global.add.f32 [%0], %1;"
                 :: "l"(addr), "f"(v) : "memory");
}

// ---------------- init ----------------
__global__ void init_kernel(const void* __restrict__ ei) {
    size_t tid    = (size_t)blockIdx.x * blockDim.x + threadIdx.x;
    size_t stride = (size_t)gridDim.x * blockDim.x;
    for (size_t i = tid; i < (size_t)NN * DMSG; i += stride) g_aggr[i] = 0.f;
    for (size_t i = tid; i < (size_t)NN; i += stride)        g_cnt[i]  = 0.f;
    if (tid == 0) {
        const unsigned long long* p = (const unsigned long long*)ei;
        int is64 = 1;
        for (int k = 0; k < 64; k++)
            if (p[k] >= (unsigned long long)NN) { is64 = 0; break; }
        g_idx64 = is64;
    }
}

// ---------------- edge kernel ----------------
#define EK_NW 10
#define EK_B  8

#define OFF_WM1 0
#define OFF_WM2 (OFF_WM1 + DIN*HMSG)            // 9216
#define OFF_WT1 (OFF_WM2 + HMSG*DMSG)           // 17408
#define OFF_BM1 (OFF_WT1 + DMSG*HTEN)           // 19456
#define OFF_BM2 (OFF_BM1 + HMSG)                // 19584
#define OFF_BT1 (OFF_BM2 + DMSG)                // 19648
#define OFF_WT2 (OFF_BT1 + HTEN)                // 19680
#define OFF_BT2 (OFF_WT2 + HTEN)                // 19712
#define OFF_IN  (OFF_BT2 + 4)                   // 19716 (16B-aligned)
#define OFF_H   (OFF_IN + EK_NW*EK_B*2*DIN)     // per-warp in: 8*144 = 1152
#define EK_SMEM_FLOATS (OFF_H + EK_NW*EK_B*2*HMSG)  // + 8*256/warp = 51716 fl (207KB)
// m_sym (duplicated, 2*DMSG=128 fl/edge, 1024/warp) overlays the IN region.

__global__ void __launch_bounds__(EK_NW * 32, 1)
edge_kernel(const float* __restrict__ x, const void* __restrict__ ei,
            const float* __restrict__ ea,
            const float* __restrict__ Wm1, const float* __restrict__ bm1,
            const float* __restrict__ Wm2, const float* __restrict__ bm2,
            const float* __restrict__ Wt1, const float* __restrict__ bt1,
            const float* __restrict__ Wt2, const float* __restrict__ bt2,
            float* __restrict__ e_out)
{
    extern __shared__ float sm[];
    for (int i = threadIdx.x; i < DIN*HMSG;  i += blockDim.x) sm[OFF_WM1+i] = Wm1[i];
    for (int i = threadIdx.x; i < HMSG*DMSG; i += blockDim.x) sm[OFF_WM2+i] = Wm2[i];
    for (int i = threadIdx.x; i < DMSG*HTEN; i += blockDim.x) sm[OFF_WT1+i] = Wt1[i];
    for (int i = threadIdx.x; i < HMSG; i += blockDim.x) sm[OFF_BM1+i] = bm1[i];
    for (int i = threadIdx.x; i < DMSG; i += blockDim.x) sm[OFF_BM2+i] = bm2[i];
    for (int i = threadIdx.x; i < HTEN; i += blockDim.x) {
        sm[OFF_BT1+i] = bt1[i];
        sm[OFF_WT2+i] = Wt2[i];
    }
    if (threadIdx.x == 0) sm[OFF_BT2] = bt2[0];
    __syncthreads();

    const int lane = threadIdx.x & 31;
    const int warp = threadIdx.x >> 5;
    const int half = lane >> 4;
    const int l16  = lane & 15;

    float* in_w = sm + OFF_IN + warp * (EK_B * 2 * DIN);    // duplicated inputs
    float* ms_w = in_w;                                     // m_sym (dup'd) overlay
    float* h_w  = sm + OFF_H  + warp * (EK_B * 2 * HMSG);   // {fwd,bwd} interleaved

    const float4 b1p  = *(const float4*)(sm + OFF_BM1 + 4*lane);
    const float4 b2p  = *(const float4*)(sm + OFF_BM2 + 4*l16);
    const float2 bt1p = *(const float2*)(sm + OFF_BT1 + 2*l16);
    const float2 wt2p = *(const float2*)(sm + OFF_WT2 + 2*l16);
    const float  bt2v = sm[OFF_BT2];

    const bool idx64 = (g_idx64 != 0);
    const long long* ei64 = (const long long*)ei;
    const int*       ei32 = (const int*)ei;

    const int gw     = blockIdx.x * EK_NW + warp;
    const int nwarps = gridDim.x * EK_NW;

    for (int base = gw * EK_B; base < NE; base += nwarps * EK_B) {
        int sr[EK_B], tg[EK_B];
        #pragma unroll
        for (int e = 0; e < EK_B; e++) {
            int id = base + e;
            if (idx64) { sr[e] = (int)ei64[id]; tg[e] = (int)ei64[NE + id]; }
            else       { sr[e] = ei32[id];      tg[e] = ei32[NE + id]; }
        }

        // ---- stage duplicated input [v0,v0,v1,v1,...] per edge ----
        #pragma unroll
        for (int e = 0; e < EK_B; e++) {
            const float2 xt = *(const float2*)(x + (size_t)tg[e]*DNODE + 2*lane);
            const float2 xs = *(const float2*)(x + (size_t)sr[e]*DNODE + 2*lane);
            float4 d;
            d.x = xt.x - xs.x; d.y = d.x;
            d.z = xt.y - xs.y; d.w = d.z;
            *(float4*)(in_w + e*(2*DIN) + 4*lane) = d;
        }
        {   // edge attrs: 32 lanes cover 8 edges x 4 float4-stores
            int e = lane >> 2, l4 = lane & 3;
            float2 ev = *(const float2*)(ea + (size_t)(base + e)*DEDGE + 2*l4);
            float4 d; d.x = ev.x; d.y = ev.x; d.z = ev.y; d.w = ev.y;
            *(float4*)(in_w + e*(2*DIN) + 2*DNODE + 4*l4) = d;
        }
        __syncwarp();

        // ---- layer 1: z = W1^T.in ; fwd = relu(z+b), bwd = relu(b-z) ----
        ull z[EK_B][2];
        #pragma unroll
        for (int e = 0; e < EK_B; e++) { z[e][0] = 0ULL; z[e][1] = 0ULL; }

        #pragma unroll 8
        for (int i = 0; i < DIN; i++) {
            ulonglong2 w2 = *(const ulonglong2*)(sm + OFF_WM1 + i*HMSG + 4*lane);
            #pragma unroll
            for (int e = 0; e < EK_B; e++) {
                ull vv = *(const ull*)(in_w + e*(2*DIN) + 2*i);
                z[e][0] = fma2(vv, w2.x, z[e][0]);
                z[e][1] = fma2(vv, w2.y, z[e][1]);
            }
        }
        #pragma unroll
        for (int e = 0; e < EK_B; e++) {
            float2 za = unpack2(z[e][0]);
            float2 zb = unpack2(z[e][1]);
            float4 h0, h1;
            h0.x = fmaxf(za.x + b1p.x, 0.f); h0.y = fmaxf(b1p.x - za.x, 0.f);
            h0.z = fmaxf(za.y + b1p.y, 0.f); h0.w = fmaxf(b1p.y - za.y, 0.f);
            h1.x = fmaxf(zb.x + b1p.z, 0.f); h1.y = fmaxf(b1p.z - zb.x, 0.f);
            h1.z = fmaxf(zb.y + b1p.w, 0.f); h1.w = fmaxf(b1p.w - zb.y, 0.f);
            *(float4*)(h_w + e*(2*HMSG) + 8*lane)     = h0;  // j=4L,4L+1 as {f,b}
            *(float4*)(h_w + e*(2*HMSG) + 8*lane + 4) = h1;  // j=4L+2,4L+3
        }
        __syncwarp();

        // ---- layer 2: half-warp h owns edges {h,2+h,4+h,6+h}; acc={fwd,bwd} ----
        ull acc[4][4];
        #pragma unroll
        for (int es = 0; es < 4; es++)
            #pragma unroll
            for (int k = 0; k < 4; k++) acc[es][k] = 0ULL;

        const float* hp0 = h_w + (0 + half)*(2*HMSG);
        const float* hp1 = h_w + (2 + half)*(2*HMSG);
        const float* hp2 = h_w + (4 + half)*(2*HMSG);
        const float* hp3 = h_w + (6 + half)*(2*HMSG);
        #pragma unroll 4
        for (int j = 0; j < HMSG; j++) {
            ulonglong2 wj = *(const ulonglong2*)(sm + OFF_WM2 + j*DMSG + 4*l16);
            float2 wlo = unpack2(wj.x);
            float2 whi = unpack2(wj.y);
            ull d0 = dup2(wlo.x), d1 = dup2(wlo.y), d2 = dup2(whi.x), d3 = dup2(whi.y);
            ull h0 = *(const ull*)(hp0 + 2*j);
            ull h1 = *(const ull*)(hp1 + 2*j);
            ull h2 = *(const ull*)(hp2 + 2*j);
            ull h3 = *(const ull*)(hp3 + 2*j);
            acc[0][0] = fma2(h0, d0, acc[0][0]);
            acc[0][1] = fma2(h0, d1, acc[0][1]);
            acc[0][2] = fma2(h0, d2, acc[0][2]);
            acc[0][3] = fma2(h0, d3, acc[0][3]);
            acc[1][0] = fma2(h1, d0, acc[1][0]);
            acc[1][1] = fma2(h1, d1, acc[1][1]);
            acc[1][2] = fma2(h1, d2, acc[1][2]);
            acc[1][3] = fma2(h1, d3, acc[1][3]);
            acc[2][0] = fma2(h2, d0, acc[2][0]);
            acc[2][1] = fma2(h2, d1, acc[2][1]);
            acc[2][2] = fma2(h2, d2, acc[2][2]);
            acc[2][3] = fma2(h2, d3, acc[2][3]);
            acc[3][0] = fma2(h3, d0, acc[3][0]);
            acc[3][1] = fma2(h3, d1, acc[3][1]);
            acc[3][2] = fma2(h3, d2, acc[3][2]);
            acc[3][3] = fma2(h3, d3, acc[3][3]);
        }

        // NOTE: ms overlay writes must come after all L1 reads of in_w (done).
        #pragma unroll
        for (int es = 0; es < 4; es++) {
            const int e = 2*es + half;
            const int t = half ? tg[2*es+1] : tg[2*es];
            const int s = half ? sr[2*es+1] : sr[2*es];
            float2 a0 = unpack2(acc[es][0]);
            float2 a1 = unpack2(acc[es][1]);
            float2 a2 = unpack2(acc[es][2]);
            float2 a3 = unpack2(acc[es][3]);
            float f0 = fmaxf(a0.x + b2p.x, 0.f), g0 = fmaxf(a0.y + b2p.x, 0.f);
            float f1 = fmaxf(a1.x + b2p.y, 0.f), g1 = fmaxf(a1.y + b2p.y, 0.f);
            float f2 = fmaxf(a2.x + b2p.z, 0.f), g2 = fmaxf(a2.y + b2p.z, 0.f);
            float f3 = fmaxf(a3.x + b2p.w, 0.f), g3 = fmaxf(a3.y + b2p.w, 0.f);
            red_add_v2(g_aggr + (size_t)t*DMSG + 4*l16,     f0, f1);
            red_add_v2(g_aggr + (size_t)t*DMSG + 4*l16 + 2, f2, f3);
            red_add_v2(g_aggr + (size_t)s*DMSG + 4*l16,     g0, g1);
            red_add_v2(g_aggr + (size_t)s*DMSG + 4*l16 + 2, g2, g3);
            // m_sym stored duplicated {v,v} for the tension f32x2 loop
            float s0 = f0+g0, s1 = f1+g1, s2 = f2+g2, s3 = f3+g3;
            float4 svA; svA.x = s0; svA.y = s0; svA.z = s1; svA.w = s1;
            float4 svB; svB.x = s2; svB.y = s2; svB.z = s3; svB.w = s3;
            *(float4*)(ms_w + e*(2*DMSG) + 8*l16)     = svA;
            *(float4*)(ms_w + e*(2*DMSG) + 8*l16 + 4) = svB;
        }
        // degree counts: one predicated RED instruction (16 lanes)
        if (lane < 2*EK_B) {
            int e = lane >> 1;
            int node = (lane & 1) ? sr[e] : tg[e];
            red_add_f32(g_cnt + node, 1.f);
        }
        __syncwarp();

        // ---- tension MLP: half-warp per edge, pre-duplicated ms ----
        #pragma unroll
        for (int p = 0; p < 4; p++) {
            const int e = 2*p + half;
            const float* msp = ms_w + e*(2*DMSG);
            ull accP = 0ULL;                 // {out 2*l16, out 2*l16+1}
            #pragma unroll 8
            for (int d = 0; d < DMSG; d++) {
                ull wv  = *(const ull*)(sm + OFF_WT1 + d*HTEN + 2*l16);
                ull svd = *(const ull*)(msp + 2*d);
                accP = fma2(svd, wv, accP);
            }
            float2 ac = unpack2(accP);
            float h0 = fmaxf(ac.x + bt1p.x, 0.f);
            float h1 = fmaxf(ac.y + bt1p.y, 0.f);
            float c  = h0*wt2p.x + h1*wt2p.y;
            #pragma unroll
            for (int off = 8; off > 0; off >>= 1)
                c += __shfl_xor_sync(0xffffffffu, c, off);
            if (l16 == 0) e_out[base + e] = c + bt2v;
        }
        __syncwarp();
    }
}

// ---------------- node kernel ----------------
#define NK_NW 16
#define NOFF_WU1 0
#define NOFF_WU2 (NOFF_WU1 + (DNODE+DMSG)*HUPD)
#define NOFF_BU1 (NOFF_WU2 + HUPD*DOUT)
#define NOFF_BU2 (NOFF_BU1 + HUPD)
#define NOFF_IN  (NOFF_BU2 + DOUT)
#define NOFF_H   (NOFF_IN + NK_NW*(DNODE+DMSG))
#define NK_SMEM_FLOATS (NOFF_H + NK_NW*HUPD)

__global__ void __launch_bounds__(NK_NW * 32, 1)
node_kernel(const float* __restrict__ x,
            const float* __restrict__ Wu1, const float* __restrict__ bu1,
            const float* __restrict__ Wu2, const float* __restrict__ bu2,
            float* __restrict__ x_out)
{
    extern __shared__ float sm[];
    for (int i = threadIdx.x; i < (DNODE+DMSG)*HUPD; i += blockDim.x) sm[NOFF_WU1+i] = Wu1[i];
    for (int i = threadIdx.x; i < HUPD*DOUT;          i += blockDim.x) sm[NOFF_WU2+i] = Wu2[i];
    for (int i = threadIdx.x; i < HUPD; i += blockDim.x) sm[NOFF_BU1+i] = bu1[i];
    for (int i = threadIdx.x; i < DOUT; i += blockDim.x) sm[NOFF_BU2+i] = bu2[i];
    __syncthreads();

    const int lane = threadIdx.x & 31;
    const int warp = threadIdx.x >> 5;
    float* in_sh = sm + NOFF_IN + warp * (DNODE + DMSG);
    float* h_sh  = sm + NOFF_H  + warp * HUPD;
    const int gw     = blockIdx.x * NK_NW + warp;
    const int nwarps = gridDim.x * NK_NW;

    for (int n = gw; n < NN; n += nwarps) {
        float inv = 1.f / fmaxf(g_cnt[n], 1.f);
        in_sh[lane]      = x[(size_t)n*DNODE + lane];
        in_sh[32 + lane] = x[(size_t)n*DNODE + 32 + lane];
        in_sh[64 + lane] = g_aggr[(size_t)n*DMSG + lane] * inv;
        in_sh[96 + lane] = g_aggr[(size_t)n*DMSG + 32 + lane] * inv;
        __syncwarp();

        float a0 = 0.f, a1 = 0.f;
        #pragma unroll 8
        for (int i = 0; i < DNODE + DMSG; i += 2) {
            float2 v = *(const float2*)&in_sh[i];
            a0 = fmaf(v.x, sm[NOFF_WU1 + i*HUPD         + lane], a0);
            a0 = fmaf(v.y, sm[NOFF_WU1 + (i+1)*HUPD     + lane], a0);
            a1 = fmaf(v.x, sm[NOFF_WU1 + i*HUPD    + 32 + lane], a1);
            a1 = fmaf(v.y, sm[NOFF_WU1 + (i+1)*HUPD + 32 + lane], a1);
        }
        h_sh[lane]      = fmaxf(a0 + sm[NOFF_BU1 + lane], 0.f);
        h_sh[32 + lane] = fmaxf(a1 + sm[NOFF_BU1 + 32 + lane], 0.f);
        __syncwarp();

        float o = 0.f;
        #pragma unroll 8
        for (int j = 0; j < HUPD; j += 2) {
            float2 v = *(const float2*)&h_sh[j];
            o = fmaf(v.x, sm[NOFF_WU2 + j*DOUT     + lane], o);
            o = fmaf(v.y, sm[NOFF_WU2 + (j+1)*DOUT + lane], o);
        }
        x_out[(size_t)n*DOUT + lane] = o + sm[NOFF_BU2 + lane];
        __syncwarp();
    }
}

// ---------------- launch ----------------
extern "C" void kernel_launch(void* const* d_in, const int* in_sizes, int n_in,
                              void* d_out, int out_size)
{
    (void)in_sizes; (void)n_in; (void)out_size;
    const float* x   = (const float*)d_in[0];
    const void*  ei  =               d_in[1];
    const float* ea  = (const float*)d_in[2];
    const float* Wm1 = (const float*)d_in[3];
    const float* bm1 = (const float*)d_in[4];
    const float* Wm2 = (const float*)d_in[5];
    const float* bm2 = (const float*)d_in[6];
    const float* Wu1 = (const float*)d_in[7];
    const float* bu1 = (const float*)d_in[8];
    const float* Wu2 = (const float*)d_in[9];
    const float* bu2 = (const float*)d_in[10];
    const float* Wt1 = (const float*)d_in[11];
    const float* bt1 = (const float*)d_in[12];
    const float* Wt2 = (const float*)d_in[13];
    const float* bt2 = (const float*)d_in[14];

    float* x_out = (float*)d_out;
    float* e_out = x_out + (size_t)NN * DOUT;

    int nsm = 148;
    cudaDeviceGetAttribute(&nsm, cudaDevAttrMultiProcessorCount, 0);

    cudaFuncSetAttribute(edge_kernel, cudaFuncAttributeMaxDynamicSharedMemorySize,
                         EK_SMEM_FLOATS * (int)sizeof(float));
    cudaFuncSetAttribute(node_kernel, cudaFuncAttributeMaxDynamicSharedMemorySize,
                         NK_SMEM_FLOATS * (int)sizeof(float));

    init_kernel<<<1024, 256>>>(ei);
    edge_kernel<<<nsm, EK_NW * 32, EK_SMEM_FLOATS * sizeof(float)>>>(
        x, ei, ea, Wm1, bm1, Wm2, bm2, Wt1, bt1, Wt2, bt2, e_out);
    node_kernel<<<nsm, NK_NW * 32, NK_SMEM_FLOATS * sizeof(float)>>>(
        x, Wu1, bu1, Wu2, bu2, x_out);
}

// round 10
// speedup vs baseline: 1.0098x; 1.0004x over previous
#include <cuda_runtime.h>
#include <cstdint>
#include <cstddef>

// ---------------- problem constants ----------------
#define NN     50000
#define NE     500000
#define DNODE  64
#define DEDGE  8
#define DIN    72
#define HMSG   128
#define DMSG   64
#define HUPD   64
#define DOUT   32
#define HTEN   32

typedef unsigned long long ull;

// ---------------- device scratch ----------------
__device__ float g_aggr[(size_t)NN * DMSG];
__device__ float g_cnt[NN];
__device__ int   g_idx64;

// ---------------- packed f32x2 helpers ----------------
__device__ __forceinline__ ull fma2(ull a, ull b, ull c) {
    ull d; asm("fma.rn.f32x2 %0, %1, %2, %3;" : "=l"(d) : "l"(a), "l"(b), "l"(c));
    return d;
}
__device__ __forceinline__ ull dup2(float x) {
    ull d; asm("mov.b64 %0, {%1, %1};" : "=l"(d) : "f"(x)); return d;
}
__device__ __forceinline__ float2 unpack2(ull v) {
    float2 r; asm("mov.b64 {%0, %1}, %2;" : "=f"(r.x), "=f"(r.y) : "l"(v)); return r;
}
__device__ __forceinline__ void red_add_v2(float* addr, float a, float b) {
    asm volatile("red.global.add.v2.f32 [%0], {%1, %2};"
                 :: "l"(addr), "f"(a), "f"(b) : "memory");
}
__device__ __forceinline__ void red_add_f32(float* addr, float v) {
    asm volatile("red.global.add.f32 [%0], %1;"
                 :: "l"(addr), "f"(v) : "memory");
}

// ---------------- init ----------------
__global__ void init_kernel(const void* __restrict__ ei) {
    size_t tid    = (size_t)blockIdx.x * blockDim.x + threadIdx.x;
    size_t stride = (size_t)gridDim.x * blockDim.x;
    for (size_t i = tid; i < (size_t)NN * DMSG; i += stride) g_aggr[i] = 0.f;
    for (size_t i = tid; i < (size_t)NN; i += stride)        g_cnt[i]  = 0.f;
    if (tid == 0) {
        const unsigned long long* p = (const unsigned long long*)ei;
        int is64 = 1;
        for (int k = 0; k < 64; k++)
            if (p[k] >= (unsigned long long)NN) { is64 = 0; break; }
        g_idx64 = is64;
    }
}

// ---------------- edge kernel ----------------
#define EK_NW 10
#define EK_B  8

#define OFF_WM1 0
#define OFF_WM2 (OFF_WM1 + DIN*HMSG)            // 9216
#define OFF_WT1 (OFF_WM2 + HMSG*DMSG)           // 17408
#define OFF_BM1 (OFF_WT1 + DMSG*HTEN)           // 19456
#define OFF_BM2 (OFF_BM1 + HMSG)                // 19584
#define OFF_BT1 (OFF_BM2 + DMSG)                // 19648
#define OFF_WT2 (OFF_BT1 + HTEN)                // 19680
#define OFF_BT2 (OFF_WT2 + HTEN)                // 19712
#define OFF_IN  (OFF_BT2 + 4)                   // 19716 (16B-aligned)
#define OFF_H   (OFF_IN + EK_NW*EK_B*2*DIN)     // per-warp in: 8*144 = 1152
#define EK_SMEM_FLOATS (OFF_H + EK_NW*EK_B*2*HMSG)  // + 8*256/warp = 51716 fl (207KB)
// m_sym (duplicated, 2*DMSG=128 fl/edge, 1024/warp) overlays the IN region.

__global__ void __launch_bounds__(EK_NW * 32, 1)
edge_kernel(const float* __restrict__ x, const void* __restrict__ ei,
            const float* __restrict__ ea,
            const float* __restrict__ Wm1, const float* __restrict__ bm1,
            const float* __restrict__ Wm2, const float* __restrict__ bm2,
            const float* __restrict__ Wt1, const float* __restrict__ bt1,
            const float* __restrict__ Wt2, const float* __restrict__ bt2,
            float* __restrict__ e_out)
{
    extern __shared__ float sm[];
    for (int i = threadIdx.x; i < DIN*HMSG;  i += blockDim.x) sm[OFF_WM1+i] = Wm1[i];
    for (int i = threadIdx.x; i < HMSG*DMSG; i += blockDim.x) sm[OFF_WM2+i] = Wm2[i];
    for (int i = threadIdx.x; i < DMSG*HTEN; i += blockDim.x) sm[OFF_WT1+i] = Wt1[i];
    for (int i = threadIdx.x; i < HMSG; i += blockDim.x) sm[OFF_BM1+i] = bm1[i];
    for (int i = threadIdx.x; i < DMSG; i += blockDim.x) sm[OFF_BM2+i] = bm2[i];
    for (int i = threadIdx.x; i < HTEN; i += blockDim.x) {
        sm[OFF_BT1+i] = bt1[i];
        sm[OFF_WT2+i] = Wt2[i];
    }
    if (threadIdx.x == 0) sm[OFF_BT2] = bt2[0];
    __syncthreads();

    const int lane = threadIdx.x & 31;
    const int warp = threadIdx.x >> 5;
    const int half = lane >> 4;
    const int l16  = lane & 15;

    float* in_w = sm + OFF_IN + warp * (EK_B * 2 * DIN);    // duplicated inputs
    float* ms_w = in_w;                                     // m_sym (dup'd) overlay
    float* h_w  = sm + OFF_H  + warp * (EK_B * 2 * HMSG);   // {fwd,bwd} interleaved

    const float4 b1p  = *(const float4*)(sm + OFF_BM1 + 4*lane);
    const float4 b2p  = *(const float4*)(sm + OFF_BM2 + 4*l16);
    const float2 bt1p = *(const float2*)(sm + OFF_BT1 + 2*l16);
    const float2 wt2p = *(const float2*)(sm + OFF_WT2 + 2*l16);
    const float  bt2v = sm[OFF_BT2];

    const bool idx64 = (g_idx64 != 0);
    const long long* ei64 = (const long long*)ei;
    const int*       ei32 = (const int*)ei;

    const int gw     = blockIdx.x * EK_NW + warp;
    const int nwarps = gridDim.x * EK_NW;

    for (int base = gw * EK_B; base < NE; base += nwarps * EK_B) {
        int sr[EK_B], tg[EK_B];
        #pragma unroll
        for (int e = 0; e < EK_B; e++) {
            int id = base + e;
            if (idx64) { sr[e] = (int)ei64[id]; tg[e] = (int)ei64[NE + id]; }
            else       { sr[e] = ei32[id];      tg[e] = ei32[NE + id]; }
        }

        // ---- stage duplicated input [v0,v0,v1,v1,...] per edge ----
        #pragma unroll
        for (int e = 0; e < EK_B; e++) {
            const float2 xt = *(const float2*)(x + (size_t)tg[e]*DNODE + 2*lane);
            const float2 xs = *(const float2*)(x + (size_t)sr[e]*DNODE + 2*lane);
            float4 d;
            d.x = xt.x - xs.x; d.y = d.x;
            d.z = xt.y - xs.y; d.w = d.z;
            *(float4*)(in_w + e*(2*DIN) + 4*lane) = d;
        }
        {   // edge attrs: 32 lanes cover 8 edges x 4 float4-stores
            int e = lane >> 2, l4 = lane & 3;
            float2 ev = *(const float2*)(ea + (size_t)(base + e)*DEDGE + 2*l4);
            float4 d; d.x = ev.x; d.y = ev.x; d.z = ev.y; d.w = ev.y;
            *(float4*)(in_w + e*(2*DIN) + 2*DNODE + 4*l4) = d;
        }
        __syncwarp();

        // ---- layer 1: z = W1^T.in ; fwd = relu(z+b), bwd = relu(b-z) ----
        ull z[EK_B][2];
        #pragma unroll
        for (int e = 0; e < EK_B; e++) { z[e][0] = 0ULL; z[e][1] = 0ULL; }

        #pragma unroll 8
        for (int i = 0; i < DIN; i++) {
            ulonglong2 w2 = *(const ulonglong2*)(sm + OFF_WM1 + i*HMSG + 4*lane);
            #pragma unroll
            for (int e = 0; e < EK_B; e++) {
                ull vv = *(const ull*)(in_w + e*(2*DIN) + 2*i);
                z[e][0] = fma2(vv, w2.x, z[e][0]);
                z[e][1] = fma2(vv, w2.y, z[e][1]);
            }
        }
        #pragma unroll
        for (int e = 0; e < EK_B; e++) {
            float2 za = unpack2(z[e][0]);
            float2 zb = unpack2(z[e][1]);
            float4 h0, h1;
            h0.x = fmaxf(za.x + b1p.x, 0.f); h0.y = fmaxf(b1p.x - za.x, 0.f);
            h0.z = fmaxf(za.y + b1p.y, 0.f); h0.w = fmaxf(b1p.y - za.y, 0.f);
            h1.x = fmaxf(zb.x + b1p.z, 0.f); h1.y = fmaxf(b1p.z - zb.x, 0.f);
            h1.z = fmaxf(zb.y + b1p.w, 0.f); h1.w = fmaxf(b1p.w - zb.y, 0.f);
            *(float4*)(h_w + e*(2*HMSG) + 8*lane)     = h0;  // j=4L,4L+1 as {f,b}
            *(float4*)(h_w + e*(2*HMSG) + 8*lane + 4) = h1;  // j=4L+2,4L+3
        }
        __syncwarp();

        // ---- layer 2: half-warp h owns edges {h,2+h,4+h,6+h}; acc={fwd,bwd} ----
        ull acc[4][4];
        #pragma unroll
        for (int es = 0; es < 4; es++)
            #pragma unroll
            for (int k = 0; k < 4; k++) acc[es][k] = 0ULL;

        const float* hp0 = h_w + (0 + half)*(2*HMSG);
        const float* hp1 = h_w + (2 + half)*(2*HMSG);
        const float* hp2 = h_w + (4 + half)*(2*HMSG);
        const float* hp3 = h_w + (6 + half)*(2*HMSG);
        #pragma unroll 4
        for (int j = 0; j < HMSG; j++) {
            ulonglong2 wj = *(const ulonglong2*)(sm + OFF_WM2 + j*DMSG + 4*l16);
            float2 wlo = unpack2(wj.x);
            float2 whi = unpack2(wj.y);
            ull d0 = dup2(wlo.x), d1 = dup2(wlo.y), d2 = dup2(whi.x), d3 = dup2(whi.y);
            ull h0 = *(const ull*)(hp0 + 2*j);
            ull h1 = *(const ull*)(hp1 + 2*j);
            ull h2 = *(const ull*)(hp2 + 2*j);
            ull h3 = *(const ull*)(hp3 + 2*j);
            acc[0][0] = fma2(h0, d0, acc[0][0]);
            acc[0][1] = fma2(h0, d1, acc[0][1]);
            acc[0][2] = fma2(h0, d2, acc[0][2]);
            acc[0][3] = fma2(h0, d3, acc[0][3]);
            acc[1][0] = fma2(h1, d0, acc[1][0]);
            acc[1][1] = fma2(h1, d1, acc[1][1]);
            acc[1][2] = fma2(h1, d2, acc[1][2]);
            acc[1][3] = fma2(h1, d3, acc[1][3]);
            acc[2][0] = fma2(h2, d0, acc[2][0]);
            acc[2][1] = fma2(h2, d1, acc[2][1]);
            acc[2][2] = fma2(h2, d2, acc[2][2]);
            acc[2][3] = fma2(h2, d3, acc[2][3]);
            acc[3][0] = fma2(h3, d0, acc[3][0]);
            acc[3][1] = fma2(h3, d1, acc[3][1]);
            acc[3][2] = fma2(h3, d2, acc[3][2]);
            acc[3][3] = fma2(h3, d3, acc[3][3]);
        }

        // NOTE: ms overlay writes must come after all L1 reads of in_w (done).
        #pragma unroll
        for (int es = 0; es < 4; es++) {
            const int e = 2*es + half;
            const int t = half ? tg[2*es+1] : tg[2*es];
            const int s = half ? sr[2*es+1] : sr[2*es];
            float2 a0 = unpack2(acc[es][0]);
            float2 a1 = unpack2(acc[es][1]);
            float2 a2 = unpack2(acc[es][2]);
            float2 a3 = unpack2(acc[es][3]);
            float f0 = fmaxf(a0.x + b2p.x, 0.f), g0 = fmaxf(a0.y + b2p.x, 0.f);
            float f1 = fmaxf(a1.x + b2p.y, 0.f), g1 = fmaxf(a1.y + b2p.y, 0.f);
            float f2 = fmaxf(a2.x + b2p.z, 0.f), g2 = fmaxf(a2.y + b2p.z, 0.f);
            float f3 = fmaxf(a3.x + b2p.w, 0.f), g3 = fmaxf(a3.y + b2p.w, 0.f);
            red_add_v2(g_aggr + (size_t)t*DMSG + 4*l16,     f0, f1);
            red_add_v2(g_aggr + (size_t)t*DMSG + 4*l16 + 2, f2, f3);
            red_add_v2(g_aggr + (size_t)s*DMSG + 4*l16,     g0, g1);
            red_add_v2(g_aggr + (size_t)s*DMSG + 4*l16 + 2, g2, g3);
            // m_sym stored duplicated {v,v} for the tension f32x2 loop
            float s0 = f0+g0, s1 = f1+g1, s2 = f2+g2, s3 = f3+g3;
            float4 svA; svA.x = s0; svA.y = s0; svA.z = s1; svA.w = s1;
            float4 svB; svB.x = s2; svB.y = s2; svB.z = s3; svB.w = s3;
            *(float4*)(ms_w + e*(2*DMSG) + 8*l16)     = svA;
            *(float4*)(ms_w + e*(2*DMSG) + 8*l16 + 4) = svB;
        }
        // degree counts: one predicated RED instruction (16 lanes)
        if (lane < 2*EK_B) {
            int e = lane >> 1;
            int node = (lane & 1) ? sr[e] : tg[e];
            red_add_f32(g_cnt + node, 1.f);
        }
        __syncwarp();

        // ---- tension MLP: half-warp per edge, pre-duplicated ms ----
        #pragma unroll
        for (int p = 0; p < 4; p++) {
            const int e = 2*p + half;
            const float* msp = ms_w + e*(2*DMSG);
            ull accP = 0ULL;                 // {out 2*l16, out 2*l16+1}
            #pragma unroll 8
            for (int d = 0; d < DMSG; d++) {
                ull wv  = *(const ull*)(sm + OFF_WT1 + d*HTEN + 2*l16);
                ull svd = *(const ull*)(msp + 2*d);
                accP = fma2(svd, wv, accP);
            }
            float2 ac = unpack2(accP);
            float h0 = fmaxf(ac.x + bt1p.x, 0.f);
            float h1 = fmaxf(ac.y + bt1p.y, 0.f);
            float c  = h0*wt2p.x + h1*wt2p.y;
            #pragma unroll
            for (int off = 8; off > 0; off >>= 1)
                c += __shfl_xor_sync(0xffffffffu, c, off);
            if (l16 == 0) e_out[base + e] = c + bt2v;
        }
        __syncwarp();
    }
}

// ---------------- node kernel ----------------
#define NK_NW 16
#define NOFF_WU1 0
#define NOFF_WU2 (NOFF_WU1 + (DNODE+DMSG)*HUPD)
#define NOFF_BU1 (NOFF_WU2 + HUPD*DOUT)
#define NOFF_BU2 (NOFF_BU1 + HUPD)
#define NOFF_IN  (NOFF_BU2 + DOUT)
#define NOFF_H   (NOFF_IN + NK_NW*(DNODE+DMSG))
#define NK_SMEM_FLOATS (NOFF_H + NK_NW*HUPD)

__global__ void __launch_bounds__(NK_NW * 32, 1)
node_kernel(const float* __restrict__ x,
            const float* __restrict__ Wu1, const float* __restrict__ bu1,
            const float* __restrict__ Wu2, const float* __restrict__ bu2,
            float* __restrict__ x_out)
{
    extern __shared__ float sm[];
    for (int i = threadIdx.x; i < (DNODE+DMSG)*HUPD; i += blockDim.x) sm[NOFF_WU1+i] = Wu1[i];
    for (int i = threadIdx.x; i < HUPD*DOUT;          i += blockDim.x) sm[NOFF_WU2+i] = Wu2[i];
    for (int i = threadIdx.x; i < HUPD; i += blockDim.x) sm[NOFF_BU1+i] = bu1[i];
    for (int i = threadIdx.x; i < DOUT; i += blockDim.x) sm[NOFF_BU2+i] = bu2[i];
    __syncthreads();

    const int lane = threadIdx.x & 31;
    const int warp = threadIdx.x >> 5;
    float* in_sh = sm + NOFF_IN + warp * (DNODE + DMSG);
    float* h_sh  = sm + NOFF_H  + warp * HUPD;
    const int gw     = blockIdx.x * NK_NW + warp;
    const int nwarps = gridDim.x * NK_NW;

    for (int n = gw; n < NN; n += nwarps) {
        float inv = 1.f / fmaxf(g_cnt[n], 1.f);
        in_sh[lane]      = x[(size_t)n*DNODE + lane];
        in_sh[32 + lane] = x[(size_t)n*DNODE + 32 + lane];
        in_sh[64 + lane] = g_aggr[(size_t)n*DMSG + lane] * inv;
        in_sh[96 + lane] = g_aggr[(size_t)n*DMSG + 32 + lane] * inv;
        __syncwarp();

        float a0 = 0.f, a1 = 0.f;
        #pragma unroll 8
        for (int i = 0; i < DNODE + DMSG; i += 2) {
            float2 v = *(const float2*)&in_sh[i];
            a0 = fmaf(v.x, sm[NOFF_WU1 + i*HUPD         + lane], a0);
            a0 = fmaf(v.y, sm[NOFF_WU1 + (i+1)*HUPD     + lane], a0);
            a1 = fmaf(v.x, sm[NOFF_WU1 + i*HUPD    + 32 + lane], a1);
            a1 = fmaf(v.y, sm[NOFF_WU1 + (i+1)*HUPD + 32 + lane], a1);
        }
        h_sh[lane]      = fmaxf(a0 + sm[NOFF_BU1 + lane], 0.f);
        h_sh[32 + lane] = fmaxf(a1 + sm[NOFF_BU1 + 32 + lane], 0.f);
        __syncwarp();

        float o = 0.f;
        #pragma unroll 8
        for (int j = 0; j < HUPD; j += 2) {
            float2 v = *(const float2*)&h_sh[j];
            o = fmaf(v.x, sm[NOFF_WU2 + j*DOUT     + lane], o);
            o = fmaf(v.y, sm[NOFF_WU2 + (j+1)*DOUT + lane], o);
        }
        x_out[(size_t)n*DOUT + lane] = o + sm[NOFF_BU2 + lane];
        __syncwarp();
    }
}

// ---------------- launch ----------------
extern "C" void kernel_launch(void* const* d_in, const int* in_sizes, int n_in,
                              void* d_out, int out_size)
{
    (void)in_sizes; (void)n_in; (void)out_size;
    const float* x   = (const float*)d_in[0];
    const void*  ei  =               d_in[1];
    const float* ea  = (const float*)d_in[2];
    const float* Wm1 = (const float*)d_in[3];
    const float* bm1 = (const float*)d_in[4];
    const float* Wm2 = (const float*)d_in[5];
    const float* bm2 = (const float*)d_in[6];
    const float* Wu1 = (const float*)d_in[7];
    const float* bu1 = (const float*)d_in[8];
    const float* Wu2 = (const float*)d_in[9];
    const float* bu2 = (const float*)d_in[10];
    const float* Wt1 = (const float*)d_in[11];
    const float* bt1 = (const float*)d_in[12];
    const float* Wt2 = (const float*)d_in[13];
    const float* bt2 = (const float*)d_in[14];

    float* x_out = (float*)d_out;
    float* e_out = x_out + (size_t)NN * DOUT;

    int nsm = 148;
    cudaDeviceGetAttribute(&nsm, cudaDevAttrMultiProcessorCount, 0);

    cudaFuncSetAttribute(edge_kernel, cudaFuncAttributeMaxDynamicSharedMemorySize,
                         EK_SMEM_FLOATS * (int)sizeof(float));
    cudaFuncSetAttribute(node_kernel, cudaFuncAttributeMaxDynamicSharedMemorySize,
                         NK_SMEM_FLOATS * (int)sizeof(float));

    init_kernel<<<1024, 256>>>(ei);
    edge_kernel<<<nsm, EK_NW * 32, EK_SMEM_FLOATS * sizeof(float)>>>(
        x, ei, ea, Wm1, bm1, Wm2, bm2, Wt1, bt1, Wt2, bt2, e_out);
    node_kernel<<<nsm, NK_NW * 32, NK_SMEM_FLOATS * sizeof(float)>>>(
        x, Wu1, bu1, Wu2, bu2, x_out);
}

// round 11
// speedup vs baseline: 1.1112x; 1.1003x over previous
#include <cuda_runtime.h>
#include <cstdint>
#include <cstddef>

// ---------------- problem constants ----------------
#define NN     50000
#define NE     500000
#define DNODE  64
#define DEDGE  8
#define DIN    72
#define HMSG   128
#define DMSG   64
#define HUPD   64
#define DOUT   32
#define HTEN   32

typedef unsigned long long ull;

// ---------------- device scratch ----------------
__device__ float g_aggr[(size_t)NN * DMSG];
__device__ float g_cnt[NN];
__device__ int   g_idx64;

// ---------------- packed f32x2 helpers ----------------
__device__ __forceinline__ ull fma2(ull a, ull b, ull c) {
    ull d; asm("fma.rn.f32x2 %0, %1, %2, %3;" : "=l"(d) : "l"(a), "l"(b), "l"(c));
    return d;
}
__device__ __forceinline__ ull dup2(float x) {
    ull d; asm("mov.b64 %0, {%1, %1};" : "=l"(d) : "f"(x)); return d;
}
__device__ __forceinline__ float2 unpack2(ull v) {
    float2 r; asm("mov.b64 {%0, %1}, %2;" : "=f"(r.x), "=f"(r.y) : "l"(v)); return r;
}
__device__ __forceinline__ void red_add_v2(float* addr, float a, float b) {
    asm volatile("red.global.add.v2.f32 [%0], {%1, %2};"
                 :: "l"(addr), "f"(a), "f"(b) : "memory");
}
__device__ __forceinline__ void red_add_f32(float* addr, float v) {
    asm volatile("red.global.add.f32 [%0], %1;"
                 :: "l"(addr), "f"(v) : "memory");
}

// ---------------- init ----------------
__global__ void init_kernel(const void* __restrict__ ei) {
    size_t tid    = (size_t)blockIdx.x * blockDim.x + threadIdx.x;
    size_t stride = (size_t)gridDim.x * blockDim.x;
    for (size_t i = tid; i < (size_t)NN * DMSG; i += stride) g_aggr[i] = 0.f;
    for (size_t i = tid; i < (size_t)NN; i += stride)        g_cnt[i]  = 0.f;
    if (tid == 0) {
        const unsigned long long* p = (const unsigned long long*)ei;
        int is64 = 1;
        for (int k = 0; k < 64; k++)
            if (p[k] >= (unsigned long long)NN) { is64 = 0; break; }
        g_idx64 = is64;
    }
}

// ---------------- edge kernel ----------------
#define EK_NW 16
#define EK_B  8
#define HCHUNK 64   // j-chunk width for the h buffer

#define OFF_WM1 0
#define OFF_WM2 (OFF_WM1 + DIN*HMSG)            // 9216
#define OFF_WT1 (OFF_WM2 + HMSG*DMSG)           // 17408
#define OFF_BM1 (OFF_WT1 + DMSG*HTEN)           // 19456
#define OFF_BM2 (OFF_BM1 + HMSG)                // 19584
#define OFF_BT1 (OFF_BM2 + DMSG)                // 19648
#define OFF_WT2 (OFF_BT1 + HTEN)                // 19680
#define OFF_BT2 (OFF_WT2 + HTEN)                // 19712
#define OFF_IN  (OFF_BT2 + 4)                   // 19716 (16B-aligned)
#define OFF_H   (OFF_IN + EK_NW*EK_B*2*DIN)     // +16*1152 = +18432
#define EK_SMEM_FLOATS (OFF_H + EK_NW*EK_B*2*HCHUNK) // +16*1024 = 54532 fl (218KB)
// m_sym (duplicated, 2*DMSG=128 fl/edge -> 1024 fl/warp) overlays the IN region.

__global__ void __launch_bounds__(EK_NW * 32, 1)
edge_kernel(const float* __restrict__ x, const void* __restrict__ ei,
            const float* __restrict__ ea,
            const float* __restrict__ Wm1, const float* __restrict__ bm1,
            const float* __restrict__ Wm2, const float* __restrict__ bm2,
            const float* __restrict__ Wt1, const float* __restrict__ bt1,
            const float* __restrict__ Wt2, const float* __restrict__ bt2,
            float* __restrict__ e_out)
{
    extern __shared__ float sm[];
    for (int i = threadIdx.x; i < DIN*HMSG;  i += blockDim.x) sm[OFF_WM1+i] = Wm1[i];
    for (int i = threadIdx.x; i < HMSG*DMSG; i += blockDim.x) sm[OFF_WM2+i] = Wm2[i];
    for (int i = threadIdx.x; i < DMSG*HTEN; i += blockDim.x) sm[OFF_WT1+i] = Wt1[i];
    for (int i = threadIdx.x; i < HMSG; i += blockDim.x) sm[OFF_BM1+i] = bm1[i];
    for (int i = threadIdx.x; i < DMSG; i += blockDim.x) sm[OFF_BM2+i] = bm2[i];
    for (int i = threadIdx.x; i < HTEN; i += blockDim.x) {
        sm[OFF_BT1+i] = bt1[i];
        sm[OFF_WT2+i] = Wt2[i];
    }
    if (threadIdx.x == 0) sm[OFF_BT2] = bt2[0];
    __syncthreads();

    const int lane = threadIdx.x & 31;
    const int warp = threadIdx.x >> 5;
    const int half = lane >> 4;
    const int l16  = lane & 15;

    float* in_w = sm + OFF_IN + warp * (EK_B * 2 * DIN);     // duplicated inputs
    float* ms_w = in_w;                                      // m_sym (dup'd) overlay
    float* h_w  = sm + OFF_H  + warp * (EK_B * 2 * HCHUNK);  // one 64-j chunk of h

    const float4 b1p  = *(const float4*)(sm + OFF_BM1 + 4*lane);
    const float4 b2p  = *(const float4*)(sm + OFF_BM2 + 4*l16);
    const float2 bt1p = *(const float2*)(sm + OFF_BT1 + 2*l16);
    const float2 wt2p = *(const float2*)(sm + OFF_WT2 + 2*l16);
    const float  bt2v = sm[OFF_BT2];

    const bool idx64 = (g_idx64 != 0);
    const long long* ei64 = (const long long*)ei;
    const int*       ei32 = (const int*)ei;

    const int gw     = blockIdx.x * EK_NW + warp;
    const int nwarps = gridDim.x * EK_NW;

    for (int base = gw * EK_B; base < NE; base += nwarps * EK_B) {
        int sr[EK_B], tg[EK_B];
        #pragma unroll
        for (int e = 0; e < EK_B; e++) {
            int id = base + e;
            if (idx64) { sr[e] = (int)ei64[id]; tg[e] = (int)ei64[NE + id]; }
            else       { sr[e] = ei32[id];      tg[e] = ei32[NE + id]; }
        }

        // ---- stage duplicated input [v0,v0,v1,v1,...] per edge ----
        #pragma unroll
        for (int e = 0; e < EK_B; e++) {
            const float2 xt = *(const float2*)(x + (size_t)tg[e]*DNODE + 2*lane);
            const float2 xs = *(const float2*)(x + (size_t)sr[e]*DNODE + 2*lane);
            float4 d;
            d.x = xt.x - xs.x; d.y = d.x;
            d.z = xt.y - xs.y; d.w = d.z;
            *(float4*)(in_w + e*(2*DIN) + 4*lane) = d;
        }
        {   // edge attrs: 32 lanes cover 8 edges x 4 float4-stores
            int e = lane >> 2, l4 = lane & 3;
            float2 ev = *(const float2*)(ea + (size_t)(base + e)*DEDGE + 2*l4);
            float4 d; d.x = ev.x; d.y = ev.x; d.z = ev.y; d.w = ev.y;
            *(float4*)(in_w + e*(2*DIN) + 2*DNODE + 4*l4) = d;
        }
        __syncwarp();

        // ---- layer 1: z = W1^T.in ; lane owns j = 4*lane .. 4*lane+3 ----
        ull z[EK_B][2];
        #pragma unroll
        for (int e = 0; e < EK_B; e++) { z[e][0] = 0ULL; z[e][1] = 0ULL; }

        #pragma unroll 8
        for (int i = 0; i < DIN; i++) {
            ulonglong2 w2 = *(const ulonglong2*)(sm + OFF_WM1 + i*HMSG + 4*lane);
            #pragma unroll
            for (int e = 0; e < EK_B; e++) {
                ull vv = *(const ull*)(in_w + e*(2*DIN) + 2*i);
                z[e][0] = fma2(vv, w2.x, z[e][0]);
                z[e][1] = fma2(vv, w2.y, z[e][1]);
            }
        }

        // ---- layer 2 in two 64-j chunks sharing one small h buffer ----
        // chunk c's rows (j in [64c, 64c+64)) are produced by half-warp c.
        ull acc[4][4];
        #pragma unroll
        for (int es = 0; es < 4; es++)
            #pragma unroll
            for (int k = 0; k < 4; k++) acc[es][k] = 0ULL;

        const float* hp0 = h_w + (0 + half)*(2*HCHUNK);
        const float* hp1 = h_w + (2 + half)*(2*HCHUNK);
        const float* hp2 = h_w + (4 + half)*(2*HCHUNK);
        const float* hp3 = h_w + (6 + half)*(2*HCHUNK);

        #pragma unroll
        for (int c = 0; c < 2; c++) {
            if (half == c) {
                #pragma unroll
                for (int e = 0; e < EK_B; e++) {
                    float2 za = unpack2(z[e][0]);
                    float2 zb = unpack2(z[e][1]);
                    float4 h0, h1;
                    h0.x = fmaxf(za.x + b1p.x, 0.f); h0.y = fmaxf(b1p.x - za.x, 0.f);
                    h0.z = fmaxf(za.y + b1p.y, 0.f); h0.w = fmaxf(b1p.y - za.y, 0.f);
                    h1.x = fmaxf(zb.x + b1p.z, 0.f); h1.y = fmaxf(b1p.z - zb.x, 0.f);
                    h1.z = fmaxf(zb.y + b1p.w, 0.f); h1.w = fmaxf(b1p.w - zb.y, 0.f);
                    *(float4*)(h_w + e*(2*HCHUNK) + 8*l16)     = h0; // {f,b} j pair
                    *(float4*)(h_w + e*(2*HCHUNK) + 8*l16 + 4) = h1;
                }
            }
            __syncwarp();

            #pragma unroll 4
            for (int jj = 0; jj < HCHUNK; jj++) {
                ulonglong2 wj = *(const ulonglong2*)(sm + OFF_WM2 + (c*HCHUNK + jj)*DMSG + 4*l16);
                float2 wlo = unpack2(wj.x);
                float2 whi = unpack2(wj.y);
                ull d0 = dup2(wlo.x), d1 = dup2(wlo.y), d2 = dup2(whi.x), d3 = dup2(whi.y);
                ull h0 = *(const ull*)(hp0 + 2*jj);
                ull h1 = *(const ull*)(hp1 + 2*jj);
                ull h2 = *(const ull*)(hp2 + 2*jj);
                ull h3 = *(const ull*)(hp3 + 2*jj);
                acc[0][0] = fma2(h0, d0, acc[0][0]);
                acc[0][1] = fma2(h0, d1, acc[0][1]);
                acc[0][2] = fma2(h0, d2, acc[0][2]);
                acc[0][3] = fma2(h0, d3, acc[0][3]);
                acc[1][0] = fma2(h1, d0, acc[1][0]);
                acc[1][1] = fma2(h1, d1, acc[1][1]);
                acc[1][2] = fma2(h1, d2, acc[1][2]);
                acc[1][3] = fma2(h1, d3, acc[1][3]);
                acc[2][0] = fma2(h2, d0, acc[2][0]);
                acc[2][1] = fma2(h2, d1, acc[2][1]);
                acc[2][2] = fma2(h2, d2, acc[2][2]);
                acc[2][3] = fma2(h2, d3, acc[2][3]);
                acc[3][0] = fma2(h3, d0, acc[3][0]);
                acc[3][1] = fma2(h3, d1, acc[3][1]);
                acc[3][2] = fma2(h3, d2, acc[3][2]);
                acc[3][3] = fma2(h3, d3, acc[3][3]);
            }
            __syncwarp();
        }

        // ---- bias+relu, RED scatter, m_sym (overlay on in_w, L1 done) ----
        #pragma unroll
        for (int es = 0; es < 4; es++) {
            const int e = 2*es + half;
            const int t = half ? tg[2*es+1] : tg[2*es];
            const int s = half ? sr[2*es+1] : sr[2*es];
            float2 a0 = unpack2(acc[es][0]);
            float2 a1 = unpack2(acc[es][1]);
            float2 a2 = unpack2(acc[es][2]);
            float2 a3 = unpack2(acc[es][3]);
            float f0 = fmaxf(a0.x + b2p.x, 0.f), g0 = fmaxf(a0.y + b2p.x, 0.f);
            float f1 = fmaxf(a1.x + b2p.y, 0.f), g1 = fmaxf(a1.y + b2p.y, 0.f);
            float f2 = fmaxf(a2.x + b2p.z, 0.f), g2 = fmaxf(a2.y + b2p.z, 0.f);
            float f3 = fmaxf(a3.x + b2p.w, 0.f), g3 = fmaxf(a3.y + b2p.w, 0.f);
            red_add_v2(g_aggr + (size_t)t*DMSG + 4*l16,     f0, f1);
            red_add_v2(g_aggr + (size_t)t*DMSG + 4*l16 + 2, f2, f3);
            red_add_v2(g_aggr + (size_t)s*DMSG + 4*l16,     g0, g1);
            red_add_v2(g_aggr + (size_t)s*DMSG + 4*l16 + 2, g2, g3);
            float s0 = f0+g0, s1 = f1+g1, s2 = f2+g2, s3 = f3+g3;
            float4 svA; svA.x = s0; svA.y = s0; svA.z = s1; svA.w = s1;
            float4 svB; svB.x = s2; svB.y = s2; svB.z = s3; svB.w = s3;
            *(float4*)(ms_w + e*(2*DMSG) + 8*l16)     = svA;
            *(float4*)(ms_w + e*(2*DMSG) + 8*l16 + 4) = svB;
        }
        if (lane < 2*EK_B) {
            int e = lane >> 1;
            int node = (lane & 1) ? sr[e] : tg[e];
            red_add_f32(g_cnt + node, 1.f);
        }
        __syncwarp();

        // ---- tension MLP: half-warp per edge, pre-duplicated ms ----
        #pragma unroll
        for (int p = 0; p < 4; p++) {
            const int e = 2*p + half;
            const float* msp = ms_w + e*(2*DMSG);
            ull accP = 0ULL;                 // {out 2*l16, out 2*l16+1}
            #pragma unroll 8
            for (int d = 0; d < DMSG; d++) {
                ull wv  = *(const ull*)(sm + OFF_WT1 + d*HTEN + 2*l16);
                ull svd = *(const ull*)(msp + 2*d);
                accP = fma2(svd, wv, accP);
            }
            float2 ac = unpack2(accP);
            float h0 = fmaxf(ac.x + bt1p.x, 0.f);
            float h1 = fmaxf(ac.y + bt1p.y, 0.f);
            float c  = h0*wt2p.x + h1*wt2p.y;
            #pragma unroll
            for (int off = 8; off > 0; off >>= 1)
                c += __shfl_xor_sync(0xffffffffu, c, off);
            if (l16 == 0) e_out[base + e] = c + bt2v;
        }
        __syncwarp();
    }
}

// ---------------- node kernel ----------------
#define NK_NW 16
#define NOFF_WU1 0
#define NOFF_WU2 (NOFF_WU1 + (DNODE+DMSG)*HUPD)
#define NOFF_BU1 (NOFF_WU2 + HUPD*DOUT)
#define NOFF_BU2 (NOFF_BU1 + HUPD)
#define NOFF_IN  (NOFF_BU2 + DOUT)
#define NOFF_H   (NOFF_IN + NK_NW*(DNODE+DMSG))
#define NK_SMEM_FLOATS (NOFF_H + NK_NW*HUPD)

__global__ void __launch_bounds__(NK_NW * 32, 1)
node_kernel(const float* __restrict__ x,
            const float* __restrict__ Wu1, const float* __restrict__ bu1,
            const float* __restrict__ Wu2, const float* __restrict__ bu2,
            float* __restrict__ x_out)
{
    extern __shared__ float sm[];
    for (int i = threadIdx.x; i < (DNODE+DMSG)*HUPD; i += blockDim.x) sm[NOFF_WU1+i] = Wu1[i];
    for (int i = threadIdx.x; i < HUPD*DOUT;          i += blockDim.x) sm[NOFF_WU2+i] = Wu2[i];
    for (int i = threadIdx.x; i < HUPD; i += blockDim.x) sm[NOFF_BU1+i] = bu1[i];
    for (int i = threadIdx.x; i < DOUT; i += blockDim.x) sm[NOFF_BU2+i] = bu2[i];
    __syncthreads();

    const int lane = threadIdx.x & 31;
    const int warp = threadIdx.x >> 5;
    float* in_sh = sm + NOFF_IN + warp * (DNODE + DMSG);
    float* h_sh  = sm + NOFF_H  + warp * HUPD;
    const int gw     = blockIdx.x * NK_NW + warp;
    const int nwarps = gridDim.x * NK_NW;

    for (int n = gw; n < NN; n += nwarps) {
        float inv = 1.f / fmaxf(g_cnt[n], 1.f);
        in_sh[lane]      = x[(size_t)n*DNODE + lane];
        in_sh[32 + lane] = x[(size_t)n*DNODE + 32 + lane];
        in_sh[64 + lane] = g_aggr[(size_t)n*DMSG + lane] * inv;
        in_sh[96 + lane] = g_aggr[(size_t)n*DMSG + 32 + lane] * inv;
        __syncwarp();

        float a0 = 0.f, a1 = 0.f;
        #pragma unroll 8
        for (int i = 0; i < DNODE + DMSG; i += 2) {
            float2 v = *(const float2*)&in_sh[i];
            a0 = fmaf(v.x, sm[NOFF_WU1 + i*HUPD         + lane], a0);
            a0 = fmaf(v.y, sm[NOFF_WU1 + (i+1)*HUPD     + lane], a0);
            a1 = fmaf(v.x, sm[NOFF_WU1 + i*HUPD    + 32 + lane], a1);
            a1 = fmaf(v.y, sm[NOFF_WU1 + (i+1)*HUPD + 32 + lane], a1);
        }
        h_sh[lane]      = fmaxf(a0 + sm[NOFF_BU1 + lane], 0.f);
        h_sh[32 + lane] = fmaxf(a1 + sm[NOFF_BU1 + 32 + lane], 0.f);
        __syncwarp();

        float o = 0.f;
        #pragma unroll 8
        for (int j = 0; j < HUPD; j += 2) {
            float2 v = *(const float2*)&h_sh[j];
            o = fmaf(v.x, sm[NOFF_WU2 + j*DOUT     + lane], o);
            o = fmaf(v.y, sm[NOFF_WU2 + (j+1)*DOUT + lane], o);
        }
        x_out[(size_t)n*DOUT + lane] = o + sm[NOFF_BU2 + lane];
        __syncwarp();
    }
}

// ---------------- launch ----------------
extern "C" void kernel_launch(void* const* d_in, const int* in_sizes, int n_in,
                              void* d_out, int out_size)
{
    (void)in_sizes; (void)n_in; (void)out_size;
    const float* x   = (const float*)d_in[0];
    const void*  ei  =               d_in[1];
    const float* ea  = (const float*)d_in[2];
    const float* Wm1 = (const float*)d_in[3];
    const float* bm1 = (const float*)d_in[4];
    const float* Wm2 = (const float*)d_in[5];
    const float* bm2 = (const float*)d_in[6];
    const float* Wu1 = (const float*)d_in[7];
    const float* bu1 = (const float*)d_in[8];
    const float* Wu2 = (const float*)d_in[9];
    const float* bu2 = (const float*)d_in[10];
    const float* Wt1 = (const float*)d_in[11];
    const float* bt1 = (const float*)d_in[12];
    const float* Wt2 = (const float*)d_in[13];
    const float* bt2 = (const float*)d_in[14];

    float* x_out = (float*)d_out;
    float* e_out = x_out + (size_t)NN * DOUT;

    int nsm = 148;
    cudaDeviceGetAttribute(&nsm, cudaDevAttrMultiProcessorCount, 0);

    cudaFuncSetAttribute(edge_kernel, cudaFuncAttributeMaxDynamicSharedMemorySize,
                         EK_SMEM_FLOATS * (int)sizeof(float));
    cudaFuncSetAttribute(node_kernel, cudaFuncAttributeMaxDynamicSharedMemorySize,
                         NK_SMEM_FLOATS * (int)sizeof(float));

    init_kernel<<<1024, 256>>>(ei);
    edge_kernel<<<nsm, EK_NW * 32, EK_SMEM_FLOATS * sizeof(float)>>>(
        x, ei, ea, Wm1, bm1, Wm2, bm2, Wt1, bt1, Wt2, bt2, e_out);
    node_kernel<<<nsm, NK_NW * 32, NK_SMEM_FLOATS * sizeof(float)>>>(
        x, Wu1, bu1, Wu2, bu2, x_out);
}

// round 12
// speedup vs baseline: 1.2356x; 1.1120x over previous
#include <cuda_runtime.h>
#include <cstdint>
#include <cstddef>

// ---------------- problem constants ----------------
#define NN     50000
#define NE     500000
#define DNODE  64
#define DEDGE  8
#define DIN    72
#define HMSG   128
#define DMSG   64
#define HUPD   64
#define DOUT   32
#define HTEN   32

typedef unsigned long long ull;

// ---------------- device scratch ----------------
__device__ float g_aggr[(size_t)NN * DMSG];
__device__ float g_cnt[NN];
__device__ int   g_idx64;

// ---------------- packed f32x2 helpers ----------------
__device__ __forceinline__ ull fma2(ull a, ull b, ull c) {
    ull d; asm("fma.rn.f32x2 %0, %1, %2, %3;" : "=l"(d) : "l"(a), "l"(b), "l"(c));
    return d;
}
__device__ __forceinline__ ull dup2(float x) {
    ull d; asm("mov.b64 %0, {%1, %1};" : "=l"(d) : "f"(x)); return d;
}
__device__ __forceinline__ float2 unpack2(ull v) {
    float2 r; asm("mov.b64 {%0, %1}, %2;" : "=f"(r.x), "=f"(r.y) : "l"(v)); return r;
}
__device__ __forceinline__ void red_add_v2(float* addr, float a, float b) {
    asm volatile("red.global.add.v2.f32 [%0], {%1, %2};"
                 :: "l"(addr), "f"(a), "f"(b) : "memory");
}
__device__ __forceinline__ void red_add_f32(float* addr, float v) {
    asm volatile("red.global.add.f32 [%0], %1;"
                 :: "l"(addr), "f"(v) : "memory");
}

// ---------------- init ----------------
__global__ void init_kernel(const void* __restrict__ ei) {
    size_t tid    = (size_t)blockIdx.x * blockDim.x + threadIdx.x;
    size_t stride = (size_t)gridDim.x * blockDim.x;
    for (size_t i = tid; i < (size_t)NN * DMSG; i += stride) g_aggr[i] = 0.f;
    for (size_t i = tid; i < (size_t)NN; i += stride)        g_cnt[i]  = 0.f;
    if (tid == 0) {
        const unsigned long long* p = (const unsigned long long*)ei;
        int is64 = 1;
        for (int k = 0; k < 64; k++)
            if (p[k] >= (unsigned long long)NN) { is64 = 0; break; }
        g_idx64 = is64;
    }
}

// ---------------- edge kernel ----------------
#define EK_NW 16
#define EK_B  8
#define HCHUNK 64   // j-chunk width for the h buffer

#define OFF_WM1 0
#define OFF_WM2 (OFF_WM1 + DIN*HMSG)            // 9216
#define OFF_WT1 (OFF_WM2 + HMSG*DMSG)           // 17408
#define OFF_BM1 (OFF_WT1 + DMSG*HTEN)           // 19456
#define OFF_BM2 (OFF_BM1 + HMSG)                // 19584
#define OFF_BT1 (OFF_BM2 + DMSG)                // 19648
#define OFF_WT2 (OFF_BT1 + HTEN)                // 19680
#define OFF_BT2 (OFF_WT2 + HTEN)                // 19712
#define OFF_IN  (OFF_BT2 + 4)                   // 19716 (16B-aligned)
#define OFF_H   (OFF_IN + EK_NW*EK_B*2*DIN)     // +16*1152 = +18432
#define EK_SMEM_FLOATS (OFF_H + EK_NW*EK_B*2*HCHUNK) // +16*1024 = 54532 fl (218KB)
// m_sym (duplicated, 2*DMSG=128 fl/edge -> 1024 fl/warp) overlays the IN region.

__global__ void __launch_bounds__(EK_NW * 32, 1)
edge_kernel(const float* __restrict__ x, const void* __restrict__ ei,
            const float* __restrict__ ea,
            const float* __restrict__ Wm1, const float* __restrict__ bm1,
            const float* __restrict__ Wm2, const float* __restrict__ bm2,
            const float* __restrict__ Wt1, const float* __restrict__ bt1,
            const float* __restrict__ Wt2, const float* __restrict__ bt2,
            float* __restrict__ e_out)
{
    extern __shared__ float sm[];
    for (int i = threadIdx.x; i < DIN*HMSG;  i += blockDim.x) sm[OFF_WM1+i] = Wm1[i];
    for (int i = threadIdx.x; i < HMSG*DMSG; i += blockDim.x) sm[OFF_WM2+i] = Wm2[i];
    for (int i = threadIdx.x; i < DMSG*HTEN; i += blockDim.x) sm[OFF_WT1+i] = Wt1[i];
    for (int i = threadIdx.x; i < HMSG; i += blockDim.x) sm[OFF_BM1+i] = bm1[i];
    for (int i = threadIdx.x; i < DMSG; i += blockDim.x) sm[OFF_BM2+i] = bm2[i];
    for (int i = threadIdx.x; i < HTEN; i += blockDim.x) {
        sm[OFF_BT1+i] = bt1[i];
        sm[OFF_WT2+i] = Wt2[i];
    }
    if (threadIdx.x == 0) sm[OFF_BT2] = bt2[0];
    __syncthreads();

    const int lane = threadIdx.x & 31;
    const int warp = threadIdx.x >> 5;
    const int half = lane >> 4;
    const int l16  = lane & 15;

    float* in_w = sm + OFF_IN + warp * (EK_B * 2 * DIN);     // duplicated inputs
    float* ms_w = in_w;                                      // m_sym (dup'd) overlay
    float* h_w  = sm + OFF_H  + warp * (EK_B * 2 * HCHUNK);  // one 64-j chunk of h

    const float4 b1p  = *(const float4*)(sm + OFF_BM1 + 4*lane);
    const float4 b2p  = *(const float4*)(sm + OFF_BM2 + 4*l16);
    const float2 bt1p = *(const float2*)(sm + OFF_BT1 + 2*l16);
    const float2 wt2p = *(const float2*)(sm + OFF_WT2 + 2*l16);
    const float  bt2v = sm[OFF_BT2];

    const bool idx64 = (g_idx64 != 0);
    const long long* ei64 = (const long long*)ei;
    const int*       ei32 = (const int*)ei;

    const int gw     = blockIdx.x * EK_NW + warp;
    const int nwarps = gridDim.x * EK_NW;

    for (int base = gw * EK_B; base < NE; base += nwarps * EK_B) {
        int sr[EK_B], tg[EK_B];
        #pragma unroll
        for (int e = 0; e < EK_B; e++) {
            int id = base + e;
            if (idx64) { sr[e] = (int)ei64[id]; tg[e] = (int)ei64[NE + id]; }
            else       { sr[e] = ei32[id];      tg[e] = ei32[NE + id]; }
        }

        // ---- stage duplicated input [v0,v0,v1,v1,...] per edge ----
        #pragma unroll
        for (int e = 0; e < EK_B; e++) {
            const float2 xt = *(const float2*)(x + (size_t)tg[e]*DNODE + 2*lane);
            const float2 xs = *(const float2*)(x + (size_t)sr[e]*DNODE + 2*lane);
            float4 d;
            d.x = xt.x - xs.x; d.y = d.x;
            d.z = xt.y - xs.y; d.w = d.z;
            *(float4*)(in_w + e*(2*DIN) + 4*lane) = d;
        }
        {   // edge attrs: 32 lanes cover 8 edges x 4 float4-stores
            int e = lane >> 2, l4 = lane & 3;
            float2 ev = *(const float2*)(ea + (size_t)(base + e)*DEDGE + 2*l4);
            float4 d; d.x = ev.x; d.y = ev.x; d.z = ev.y; d.w = ev.y;
            *(float4*)(in_w + e*(2*DIN) + 2*DNODE + 4*l4) = d;
        }
        __syncwarp();

        // ---- layer 1: z = W1^T.in ; lane owns j = 4*lane .. 4*lane+3 ----
        ull z[EK_B][2];
        #pragma unroll
        for (int e = 0; e < EK_B; e++) { z[e][0] = 0ULL; z[e][1] = 0ULL; }

        #pragma unroll 8
        for (int i = 0; i < DIN; i++) {
            ulonglong2 w2 = *(const ulonglong2*)(sm + OFF_WM1 + i*HMSG + 4*lane);
            #pragma unroll
            for (int e = 0; e < EK_B; e++) {
                ull vv = *(const ull*)(in_w + e*(2*DIN) + 2*i);
                z[e][0] = fma2(vv, w2.x, z[e][0]);
                z[e][1] = fma2(vv, w2.y, z[e][1]);
            }
        }

        // ---- layer 2 in two 64-j chunks sharing one small h buffer ----
        // chunk c's rows (j in [64c, 64c+64)) are produced by half-warp c.
        ull acc[4][4];
        #pragma unroll
        for (int es = 0; es < 4; es++)
            #pragma unroll
            for (int k = 0; k < 4; k++) acc[es][k] = 0ULL;

        const float* hp0 = h_w + (0 + half)*(2*HCHUNK);
        const float* hp1 = h_w + (2 + half)*(2*HCHUNK);
        const float* hp2 = h_w + (4 + half)*(2*HCHUNK);
        const float* hp3 = h_w + (6 + half)*(2*HCHUNK);

        #pragma unroll
        for (int c = 0; c < 2; c++) {
            if (half == c) {
                #pragma unroll
                for (int e = 0; e < EK_B; e++) {
                    float2 za = unpack2(z[e][0]);
                    float2 zb = unpack2(z[e][1]);
                    float4 h0, h1;
                    h0.x = fmaxf(za.x + b1p.x, 0.f); h0.y = fmaxf(b1p.x - za.x, 0.f);
                    h0.z = fmaxf(za.y + b1p.y, 0.f); h0.w = fmaxf(b1p.y - za.y, 0.f);
                    h1.x = fmaxf(zb.x + b1p.z, 0.f); h1.y = fmaxf(b1p.z - zb.x, 0.f);
                    h1.z = fmaxf(zb.y + b1p.w, 0.f); h1.w = fmaxf(b1p.w - zb.y, 0.f);
                    *(float4*)(h_w + e*(2*HCHUNK) + 8*l16)     = h0; // {f,b} j pair
                    *(float4*)(h_w + e*(2*HCHUNK) + 8*l16 + 4) = h1;
                }
            }
            __syncwarp();

            // 2 j's per step: weights for rows jj, jj+1; h loaded as ulonglong2
            // {f_jj,b_jj,f_jj+1,b_jj+1}.
            #pragma unroll 2
            for (int jj = 0; jj < HCHUNK; jj += 2) {
                const float* wrow = sm + OFF_WM2 + (c*HCHUNK + jj)*DMSG + 4*l16;
                ulonglong2 wj0 = *(const ulonglong2*)wrow;
                ulonglong2 wj1 = *(const ulonglong2*)(wrow + DMSG);
                float2 w0lo = unpack2(wj0.x), w0hi = unpack2(wj0.y);
                float2 w1lo = unpack2(wj1.x), w1hi = unpack2(wj1.y);
                ull a0 = dup2(w0lo.x), a1 = dup2(w0lo.y), a2 = dup2(w0hi.x), a3 = dup2(w0hi.y);
                ull b0 = dup2(w1lo.x), b1 = dup2(w1lo.y), b2 = dup2(w1hi.x), b3 = dup2(w1hi.y);
                ulonglong2 hA = *(const ulonglong2*)(hp0 + 2*jj);
                ulonglong2 hB = *(const ulonglong2*)(hp1 + 2*jj);
                ulonglong2 hC = *(const ulonglong2*)(hp2 + 2*jj);
                ulonglong2 hD = *(const ulonglong2*)(hp3 + 2*jj);
                acc[0][0] = fma2(hA.x, a0, acc[0][0]);
                acc[0][1] = fma2(hA.x, a1, acc[0][1]);
                acc[0][2] = fma2(hA.x, a2, acc[0][2]);
                acc[0][3] = fma2(hA.x, a3, acc[0][3]);
                acc[1][0] = fma2(hB.x, a0, acc[1][0]);
                acc[1][1] = fma2(hB.x, a1, acc[1][1]);
                acc[1][2] = fma2(hB.x, a2, acc[1][2]);
                acc[1][3] = fma2(hB.x, a3, acc[1][3]);
                acc[2][0] = fma2(hC.x, a0, acc[2][0]);
                acc[2][1] = fma2(hC.x, a1, acc[2][1]);
                acc[2][2] = fma2(hC.x, a2, acc[2][2]);
                acc[2][3] = fma2(hC.x, a3, acc[2][3]);
                acc[3][0] = fma2(hD.x, a0, acc[3][0]);
                acc[3][1] = fma2(hD.x, a1, acc[3][1]);
                acc[3][2] = fma2(hD.x, a2, acc[3][2]);
                acc[3][3] = fma2(hD.x, a3, acc[3][3]);
                acc[0][0] = fma2(hA.y, b0, acc[0][0]);
                acc[0][1] = fma2(hA.y, b1, acc[0][1]);
                acc[0][2] = fma2(hA.y, b2, acc[0][2]);
                acc[0][3] = fma2(hA.y, b3, acc[0][3]);
                acc[1][0] = fma2(hB.y, b0, acc[1][0]);
                acc[1][1] = fma2(hB.y, b1, acc[1][1]);
                acc[1][2] = fma2(hB.y, b2, acc[1][2]);
                acc[1][3] = fma2(hB.y, b3, acc[1][3]);
                acc[2][0] = fma2(hC.y, b0, acc[2][0]);
                acc[2][1] = fma2(hC.y, b1, acc[2][1]);
                acc[2][2] = fma2(hC.y, b2, acc[2][2]);
                acc[2][3] = fma2(hC.y, b3, acc[2][3]);
                acc[3][0] = fma2(hD.y, b0, acc[3][0]);
                acc[3][1] = fma2(hD.y, b1, acc[3][1]);
                acc[3][2] = fma2(hD.y, b2, acc[3][2]);
                acc[3][3] = fma2(hD.y, b3, acc[3][3]);
            }
            __syncwarp();
        }

        // ---- bias+relu, RED scatter, m_sym (overlay on in_w, L1 done) ----
        #pragma unroll
        for (int es = 0; es < 4; es++) {
            const int e = 2*es + half;
            const int t = half ? tg[2*es+1] : tg[2*es];
            const int s = half ? sr[2*es+1] : sr[2*es];
            float2 a0 = unpack2(acc[es][0]);
            float2 a1 = unpack2(acc[es][1]);
            float2 a2 = unpack2(acc[es][2]);
            float2 a3 = unpack2(acc[es][3]);
            float f0 = fmaxf(a0.x + b2p.x, 0.f), g0 = fmaxf(a0.y + b2p.x, 0.f);
            float f1 = fmaxf(a1.x + b2p.y, 0.f), g1 = fmaxf(a1.y + b2p.y, 0.f);
            float f2 = fmaxf(a2.x + b2p.z, 0.f), g2 = fmaxf(a2.y + b2p.z, 0.f);
            float f3 = fmaxf(a3.x + b2p.w, 0.f), g3 = fmaxf(a3.y + b2p.w, 0.f);
            red_add_v2(g_aggr + (size_t)t*DMSG + 4*l16,     f0, f1);
            red_add_v2(g_aggr + (size_t)t*DMSG + 4*l16 + 2, f2, f3);
            red_add_v2(g_aggr + (size_t)s*DMSG + 4*l16,     g0, g1);
            red_add_v2(g_aggr + (size_t)s*DMSG + 4*l16 + 2, g2, g3);
            float s0 = f0+g0, s1 = f1+g1, s2 = f2+g2, s3 = f3+g3;
            float4 svA; svA.x = s0; svA.y = s0; svA.z = s1; svA.w = s1;
            float4 svB; svB.x = s2; svB.y = s2; svB.z = s3; svB.w = s3;
            *(float4*)(ms_w + e*(2*DMSG) + 8*l16)     = svA;
            *(float4*)(ms_w + e*(2*DMSG) + 8*l16 + 4) = svB;
        }
        if (lane < 2*EK_B) {
            int e = lane >> 1;
            int node = (lane & 1) ? sr[e] : tg[e];
            red_add_f32(g_cnt + node, 1.f);
        }
        __syncwarp();

        // ---- tension MLP: all 8 edges in one d-loop, weights loaded once ----
        ull tac[4];
        tac[0] = 0ULL; tac[1] = 0ULL; tac[2] = 0ULL; tac[3] = 0ULL;
        #pragma unroll 4
        for (int d = 0; d < DMSG; d += 2) {
            ull w0 = *(const ull*)(sm + OFF_WT1 + d*HTEN     + 2*l16);
            ull w1 = *(const ull*)(sm + OFF_WT1 + (d+1)*HTEN + 2*l16);
            #pragma unroll
            for (int p = 0; p < 4; p++) {
                const float* msp = ms_w + (2*p + half)*(2*DMSG);
                ulonglong2 mv = *(const ulonglong2*)(msp + 2*d); // {s_d,s_d,s_d1,s_d1}
                tac[p] = fma2(mv.x, w0, tac[p]);
                tac[p] = fma2(mv.y, w1, tac[p]);
            }
        }
        #pragma unroll
        for (int p = 0; p < 4; p++) {
            float2 ac = unpack2(tac[p]);
            float h0 = fmaxf(ac.x + bt1p.x, 0.f);
            float h1 = fmaxf(ac.y + bt1p.y, 0.f);
            float c  = h0*wt2p.x + h1*wt2p.y;
            #pragma unroll
            for (int off = 8; off > 0; off >>= 1)
                c += __shfl_xor_sync(0xffffffffu, c, off);
            if (l16 == 0) e_out[base + 2*p + half] = c + bt2v;
        }
        __syncwarp();
    }
}

// ---------------- node kernel ----------------
#define NK_NW 16
#define NOFF_WU1 0
#define NOFF_WU2 (NOFF_WU1 + (DNODE+DMSG)*HUPD)
#define NOFF_BU1 (NOFF_WU2 + HUPD*DOUT)
#define NOFF_BU2 (NOFF_BU1 + HUPD)
#define NOFF_IN  (NOFF_BU2 + DOUT)
#define NOFF_H   (NOFF_IN + NK_NW*(DNODE+DMSG))
#define NK_SMEM_FLOATS (NOFF_H + NK_NW*HUPD)

__global__ void __launch_bounds__(NK_NW * 32, 1)
node_kernel(const float* __restrict__ x,
            const float* __restrict__ Wu1, const float* __restrict__ bu1,
            const float* __restrict__ Wu2, const float* __restrict__ bu2,
            float* __restrict__ x_out)
{
    extern __shared__ float sm[];
    for (int i = threadIdx.x; i < (DNODE+DMSG)*HUPD; i += blockDim.x) sm[NOFF_WU1+i] = Wu1[i];
    for (int i = threadIdx.x; i < HUPD*DOUT;          i += blockDim.x) sm[NOFF_WU2+i] = Wu2[i];
    for (int i = threadIdx.x; i < HUPD; i += blockDim.x) sm[NOFF_BU1+i] = bu1[i];
    for (int i = threadIdx.x; i < DOUT; i += blockDim.x) sm[NOFF_BU2+i] = bu2[i];
    __syncthreads();

    const int lane = threadIdx.x & 31;
    const int warp = threadIdx.x >> 5;
    float* in_sh = sm + NOFF_IN + warp * (DNODE + DMSG);
    float* h_sh  = sm + NOFF_H  + warp * HUPD;
    const int gw     = blockIdx.x * NK_NW + warp;
    const int nwarps = gridDim.x * NK_NW;

    for (int n = gw; n < NN; n += nwarps) {
        float inv = 1.f / fmaxf(g_cnt[n], 1.f);
        in_sh[lane]      = x[(size_t)n*DNODE + lane];
        in_sh[32 + lane] = x[(size_t)n*DNODE + 32 + lane];
        in_sh[64 + lane] = g_aggr[(size_t)n*DMSG + lane] * inv;
        in_sh[96 + lane] = g_aggr[(size_t)n*DMSG + 32 + lane] * inv;
        __syncwarp();

        float a0 = 0.f, a1 = 0.f;
        #pragma unroll 8
        for (int i = 0; i < DNODE + DMSG; i += 2) {
            float2 v = *(const float2*)&in_sh[i];
            a0 = fmaf(v.x, sm[NOFF_WU1 + i*HUPD         + lane], a0);
            a0 = fmaf(v.y, sm[NOFF_WU1 + (i+1)*HUPD     + lane], a0);
            a1 = fmaf(v.x, sm[NOFF_WU1 + i*HUPD    + 32 + lane], a1);
            a1 = fmaf(v.y, sm[NOFF_WU1 + (i+1)*HUPD + 32 + lane], a1);
        }
        h_sh[lane]      = fmaxf(a0 + sm[NOFF_BU1 + lane], 0.f);
        h_sh[32 + lane] = fmaxf(a1 + sm[NOFF_BU1 + 32 + lane], 0.f);
        __syncwarp();

        float o = 0.f;
        #pragma unroll 8
        for (int j = 0; j < HUPD; j += 2) {
            float2 v = *(const float2*)&h_sh[j];
            o = fmaf(v.x, sm[NOFF_WU2 + j*DOUT     + lane], o);
            o = fmaf(v.y, sm[NOFF_WU2 + (j+1)*DOUT + lane], o);
        }
        x_out[(size_t)n*DOUT + lane] = o + sm[NOFF_BU2 + lane];
        __syncwarp();
    }
}

// ---------------- launch ----------------
extern "C" void kernel_launch(void* const* d_in, const int* in_sizes, int n_in,
                              void* d_out, int out_size)
{
    (void)in_sizes; (void)n_in; (void)out_size;
    const float* x   = (const float*)d_in[0];
    const void*  ei  =               d_in[1];
    const float* ea  = (const float*)d_in[2];
    const float* Wm1 = (const float*)d_in[3];
    const float* bm1 = (const float*)d_in[4];
    const float* Wm2 = (const float*)d_in[5];
    const float* bm2 = (const float*)d_in[6];
    const float* Wu1 = (const float*)d_in[7];
    const float* bu1 = (const float*)d_in[8];
    const float* Wu2 = (const float*)d_in[9];
    const float* bu2 = (const float*)d_in[10];
    const float* Wt1 = (const float*)d_in[11];
    const float* bt1 = (const float*)d_in[12];
    const float* Wt2 = (const float*)d_in[13];
    const float* bt2 = (const float*)d_in[14];

    float* x_out = (float*)d_out;
    float* e_out = x_out + (size_t)NN * DOUT;

    int nsm = 148;
    cudaDeviceGetAttribute(&nsm, cudaDevAttrMultiProcessorCount, 0);

    cudaFuncSetAttribute(edge_kernel, cudaFuncAttributeMaxDynamicSharedMemorySize,
                         EK_SMEM_FLOATS * (int)sizeof(float));
    cudaFuncSetAttribute(node_kernel, cudaFuncAttributeMaxDynamicSharedMemorySize,
                         NK_SMEM_FLOATS * (int)sizeof(float));

    init_kernel<<<1024, 256>>>(ei);
    edge_kernel<<<nsm, EK_NW * 32, EK_SMEM_FLOATS * sizeof(float)>>>(
        x, ei, ea, Wm1, bm1, Wm2, bm2, Wt1, bt1, Wt2, bt2, e_out);
    node_kernel<<<nsm, NK_NW * 32, NK_SMEM_FLOATS * sizeof(float)>>>(
        x, Wu1, bu1, Wu2, bu2, x_out);
}

// round 13
// speedup vs baseline: 1.4600x; 1.1815x over previous
#include <cuda_runtime.h>
#include <cstdint>
#include <cstddef>

// ---------------- problem constants ----------------
#define NN     50000
#define NE     500000
#define DNODE  64
#define DEDGE  8
#define DIN    72
#define HMSG   128
#define DMSG   64
#define HUPD   64
#define DOUT   32
#define HTEN   32

typedef unsigned long long ull;

// ---------------- device scratch ----------------
__device__ float g_aggr[(size_t)NN * DMSG];
__device__ float g_cnt[NN];
__device__ float g_y[(size_t)NN * HMSG];     // y = x @ Wm1[0:64]  (25.6 MB)
__device__ int   g_idx64;

// ---------------- packed f32x2 helpers ----------------
__device__ __forceinline__ ull fma2(ull a, ull b, ull c) {
    ull d; asm("fma.rn.f32x2 %0, %1, %2, %3;" : "=l"(d) : "l"(a), "l"(b), "l"(c));
    return d;
}
__device__ __forceinline__ ull dup2(float x) {
    ull d; asm("mov.b64 %0, {%1, %1};" : "=l"(d) : "f"(x)); return d;
}
__device__ __forceinline__ float2 unpack2(ull v) {
    float2 r; asm("mov.b64 {%0, %1}, %2;" : "=f"(r.x), "=f"(r.y) : "l"(v)); return r;
}
__device__ __forceinline__ void red_add_v2(float* addr, float a, float b) {
    asm volatile("red.global.add.v2.f32 [%0], {%1, %2};"
                 :: "l"(addr), "f"(a), "f"(b) : "memory");
}
__device__ __forceinline__ void red_add_f32(float* addr, float v) {
    asm volatile("red.global.add.f32 [%0], %1;"
                 :: "l"(addr), "f"(v) : "memory");
}

// ---------------- init ----------------
__global__ void init_kernel(const void* __restrict__ ei) {
    size_t tid    = (size_t)blockIdx.x * blockDim.x + threadIdx.x;
    size_t stride = (size_t)gridDim.x * blockDim.x;
    for (size_t i = tid; i < (size_t)NN * DMSG; i += stride) g_aggr[i] = 0.f;
    for (size_t i = tid; i < (size_t)NN; i += stride)        g_cnt[i]  = 0.f;
    if (tid == 0) {
        const unsigned long long* p = (const unsigned long long*)ei;
        int is64 = 1;
        for (int k = 0; k < 64; k++)
            if (p[k] >= (unsigned long long)NN) { is64 = 0; break; }
        g_idx64 = is64;
    }
}

// ---------------- precompute y = x @ Wm1[0:64,:]  ----------------
#define PY_NW 16
#define PYOFF_W 0                              // 64*128 = 8192 fl
#define PYOFF_X (PYOFF_W + DNODE*HMSG)         // dup'd x: 128 fl/warp
#define PY_SMEM_FLOATS (PYOFF_X + PY_NW*2*DNODE)

__global__ void __launch_bounds__(PY_NW * 32, 1)
precompute_y_kernel(const float* __restrict__ x, const float* __restrict__ Wm1)
{
    extern __shared__ float sm[];
    for (int i = threadIdx.x; i < DNODE*HMSG; i += blockDim.x) sm[PYOFF_W+i] = Wm1[i];
    __syncthreads();

    const int lane = threadIdx.x & 31;
    const int warp = threadIdx.x >> 5;
    float* xs_w = sm + PYOFF_X + warp * (2*DNODE);

    const int gw     = blockIdx.x * PY_NW + warp;
    const int nwarps = gridDim.x * PY_NW;

    for (int n = gw; n < NN; n += nwarps) {
        const float2 xv = *(const float2*)(x + (size_t)n*DNODE + 2*lane);
        float4 d; d.x = xv.x; d.y = xv.x; d.z = xv.y; d.w = xv.y;
        *(float4*)(xs_w + 4*lane) = d;
        __syncwarp();

        ull a0 = 0ULL, a1 = 0ULL;
        #pragma unroll 8
        for (int i = 0; i < DNODE; i++) {
            ulonglong2 w2 = *(const ulonglong2*)(sm + PYOFF_W + i*HMSG + 4*lane);
            ull vv = *(const ull*)(xs_w + 2*i);
            a0 = fma2(vv, w2.x, a0);
            a1 = fma2(vv, w2.y, a1);
        }
        ulonglong2 o; o.x = a0; o.y = a1;
        *(ulonglong2*)(g_y + (size_t)n*HMSG + 4*lane) = o;
        __syncwarp();
    }
}

// ---------------- edge kernel ----------------
#define EK_NW 16
#define EK_B  8
#define HCHUNK 64

#define OFF_WM1 0
#define OFF_WM2 (OFF_WM1 + DIN*HMSG)            // 9216
#define OFF_WT1 (OFF_WM2 + HMSG*DMSG)           // 17408
#define OFF_BM1 (OFF_WT1 + DMSG*HTEN)           // 19456
#define OFF_BM2 (OFF_BM1 + HMSG)                // 19584
#define OFF_BT1 (OFF_BM2 + DMSG)                // 19648
#define OFF_WT2 (OFF_BT1 + HTEN)                // 19680
#define OFF_BT2 (OFF_WT2 + HTEN)                // 19712
#define OFF_EA  (OFF_BT2 + 4)                   // 19716, 16B aligned
#define OFF_MS  (OFF_EA + EK_NW*EK_B*2*DEDGE)   // +16*128  = 21764
#define OFF_H   (OFF_MS + EK_NW*EK_B*2*DMSG)    // +16*1024 = 38148
#define EK_SMEM_FLOATS (OFF_H + EK_NW*EK_B*2*HCHUNK) // +16*1024 = 54532 fl (218KB)

__global__ void __launch_bounds__(EK_NW * 32, 1)
edge_kernel(const void* __restrict__ ei,
            const float* __restrict__ ea,
            const float* __restrict__ Wm1, const float* __restrict__ bm1,
            const float* __restrict__ Wm2, const float* __restrict__ bm2,
            const float* __restrict__ Wt1, const float* __restrict__ bt1,
            const float* __restrict__ Wt2, const float* __restrict__ bt2,
            float* __restrict__ e_out)
{
    extern __shared__ float sm[];
    for (int i = threadIdx.x; i < DIN*HMSG;  i += blockDim.x) sm[OFF_WM1+i] = Wm1[i];
    for (int i = threadIdx.x; i < HMSG*DMSG; i += blockDim.x) sm[OFF_WM2+i] = Wm2[i];
    for (int i = threadIdx.x; i < DMSG*HTEN; i += blockDim.x) sm[OFF_WT1+i] = Wt1[i];
    for (int i = threadIdx.x; i < HMSG; i += blockDim.x) sm[OFF_BM1+i] = bm1[i];
    for (int i = threadIdx.x; i < DMSG; i += blockDim.x) sm[OFF_BM2+i] = bm2[i];
    for (int i = threadIdx.x; i < HTEN; i += blockDim.x) {
        sm[OFF_BT1+i] = bt1[i];
        sm[OFF_WT2+i] = Wt2[i];
    }
    if (threadIdx.x == 0) sm[OFF_BT2] = bt2[0];
    __syncthreads();

    const int lane = threadIdx.x & 31;
    const int warp = threadIdx.x >> 5;
    const int half = lane >> 4;
    const int l16  = lane & 15;

    float* ea_w = sm + OFF_EA + warp * (EK_B * 2 * DEDGE);   // dup'd edge attrs
    float* ms_w = sm + OFF_MS + warp * (EK_B * 2 * DMSG);    // dup'd m_sym
    float* h_w  = sm + OFF_H  + warp * (EK_B * 2 * HCHUNK);  // one 64-j chunk of h

    const float4 b1p  = *(const float4*)(sm + OFF_BM1 + 4*lane);
    const float4 b2p  = *(const float4*)(sm + OFF_BM2 + 4*l16);
    const float2 bt1p = *(const float2*)(sm + OFF_BT1 + 2*l16);
    const float2 wt2p = *(const float2*)(sm + OFF_WT2 + 2*l16);
    const float  bt2v = sm[OFF_BT2];
    const ull    NEG1 = dup2(-1.0f);

    const bool idx64 = (g_idx64 != 0);
    const long long* ei64 = (const long long*)ei;
    const int*       ei32 = (const int*)ei;

    const int gw     = blockIdx.x * EK_NW + warp;
    const int nwarps = gridDim.x * EK_NW;

    for (int base = gw * EK_B; base < NE; base += nwarps * EK_B) {
        int sr[EK_B], tg[EK_B];
        #pragma unroll
        for (int e = 0; e < EK_B; e++) {
            int id = base + e;
            if (idx64) { sr[e] = (int)ei64[id]; tg[e] = (int)ei64[NE + id]; }
            else       { sr[e] = ei32[id];      tg[e] = ei32[NE + id]; }
        }

        // ---- stage duplicated edge attrs ----
        {
            int e = lane >> 2, l4 = lane & 3;
            float2 ev = *(const float2*)(ea + (size_t)(base + e)*DEDGE + 2*l4);
            float4 d; d.x = ev.x; d.y = ev.x; d.z = ev.y; d.w = ev.y;
            *(float4*)(ea_w + e*(2*DEDGE) + 4*l4) = d;
        }
        __syncwarp();

        // ---- layer 1 via precomputed y: z = y[t] - y[s] + Wm1[64:72]^T ea ----
        // lane owns j = 4*lane .. 4*lane+3 (== its float4 slice of the y rows)
        ull z[EK_B][2];
        #pragma unroll
        for (int e = 0; e < EK_B; e++) {
            ulonglong2 yt = *(const ulonglong2*)(g_y + (size_t)tg[e]*HMSG + 4*lane);
            ulonglong2 ys = *(const ulonglong2*)(g_y + (size_t)sr[e]*HMSG + 4*lane);
            z[e][0] = fma2(ys.x, NEG1, yt.x);
            z[e][1] = fma2(ys.y, NEG1, yt.y);
        }
        #pragma unroll
        for (int i = 0; i < DEDGE; i++) {
            ulonglong2 w2 = *(const ulonglong2*)(sm + OFF_WM1 + (DNODE+i)*HMSG + 4*lane);
            #pragma unroll
            for (int e = 0; e < EK_B; e++) {
                ull vv = *(const ull*)(ea_w + e*(2*DEDGE) + 2*i);
                z[e][0] = fma2(vv, w2.x, z[e][0]);
                z[e][1] = fma2(vv, w2.y, z[e][1]);
            }
        }

        // ---- layer 2 in two 64-j chunks sharing one small h buffer ----
        ull acc[4][4];
        #pragma unroll
        for (int es = 0; es < 4; es++)
            #pragma unroll
            for (int k = 0; k < 4; k++) acc[es][k] = 0ULL;

        const float* hp0 = h_w + (0 + half)*(2*HCHUNK);
        const float* hp1 = h_w + (2 + half)*(2*HCHUNK);
        const float* hp2 = h_w + (4 + half)*(2*HCHUNK);
        const float* hp3 = h_w + (6 + half)*(2*HCHUNK);

        #pragma unroll
        for (int c = 0; c < 2; c++) {
            if (half == c) {
                #pragma unroll
                for (int e = 0; e < EK_B; e++) {
                    float2 za = unpack2(z[e][0]);
                    float2 zb = unpack2(z[e][1]);
                    float4 h0, h1;
                    h0.x = fmaxf(za.x + b1p.x, 0.f); h0.y = fmaxf(b1p.x - za.x, 0.f);
                    h0.z = fmaxf(za.y + b1p.y, 0.f); h0.w = fmaxf(b1p.y - za.y, 0.f);
                    h1.x = fmaxf(zb.x + b1p.z, 0.f); h1.y = fmaxf(b1p.z - zb.x, 0.f);
                    h1.z = fmaxf(zb.y + b1p.w, 0.f); h1.w = fmaxf(b1p.w - zb.y, 0.f);
                    *(float4*)(h_w + e*(2*HCHUNK) + 8*l16)     = h0; // {f,b} j pair
                    *(float4*)(h_w + e*(2*HCHUNK) + 8*l16 + 4) = h1;
                }
            }
            __syncwarp();

            #pragma unroll 2
            for (int jj = 0; jj < HCHUNK; jj += 2) {
                const float* wrow = sm + OFF_WM2 + (c*HCHUNK + jj)*DMSG + 4*l16;
                ulonglong2 wj0 = *(const ulonglong2*)wrow;
                ulonglong2 wj1 = *(const ulonglong2*)(wrow + DMSG);
                float2 w0lo = unpack2(wj0.x), w0hi = unpack2(wj0.y);
                float2 w1lo = unpack2(wj1.x), w1hi = unpack2(wj1.y);
                ull a0 = dup2(w0lo.x), a1 = dup2(w0lo.y), a2 = dup2(w0hi.x), a3 = dup2(w0hi.y);
                ull b0 = dup2(w1lo.x), b1 = dup2(w1lo.y), b2 = dup2(w1hi.x), b3 = dup2(w1hi.y);
                ulonglong2 hA = *(const ulonglong2*)(hp0 + 2*jj);
                ulonglong2 hB = *(const ulonglong2*)(hp1 + 2*jj);
                ulonglong2 hC = *(const ulonglong2*)(hp2 + 2*jj);
                ulonglong2 hD = *(const ulonglong2*)(hp3 + 2*jj);
                acc[0][0] = fma2(hA.x, a0, acc[0][0]);
                acc[0][1] = fma2(hA.x, a1, acc[0][1]);
                acc[0][2] = fma2(hA.x, a2, acc[0][2]);
                acc[0][3] = fma2(hA.x, a3, acc[0][3]);
                acc[1][0] = fma2(hB.x, a0, acc[1][0]);
                acc[1][1] = fma2(hB.x, a1, acc[1][1]);
                acc[1][2] = fma2(hB.x, a2, acc[1][2]);
                acc[1][3] = fma2(hB.x, a3, acc[1][3]);
                acc[2][0] = fma2(hC.x, a0, acc[2][0]);
                acc[2][1] = fma2(hC.x, a1, acc[2][1]);
                acc[2][2] = fma2(hC.x, a2, acc[2][2]);
                acc[2][3] = fma2(hC.x, a3, acc[2][3]);
                acc[3][0] = fma2(hD.x, a0, acc[3][0]);
                acc[3][1] = fma2(hD.x, a1, acc[3][1]);
                acc[3][2] = fma2(hD.x, a2, acc[3][2]);
                acc[3][3] = fma2(hD.x, a3, acc[3][3]);
                acc[0][0] = fma2(hA.y, b0, acc[0][0]);
                acc[0][1] = fma2(hA.y, b1, acc[0][1]);
                acc[0][2] = fma2(hA.y, b2, acc[0][2]);
                acc[0][3] = fma2(hA.y, b3, acc[0][3]);
                acc[1][0] = fma2(hB.y, b0, acc[1][0]);
                acc[1][1] = fma2(hB.y, b1, acc[1][1]);
                acc[1][2] = fma2(hB.y, b2, acc[1][2]);
                acc[1][3] = fma2(hB.y, b3, acc[1][3]);
                acc[2][0] = fma2(hC.y, b0, acc[2][0]);
                acc[2][1] = fma2(hC.y, b1, acc[2][1]);
                acc[2][2] = fma2(hC.y, b2, acc[2][2]);
                acc[2][3] = fma2(hC.y, b3, acc[2][3]);
                acc[3][0] = fma2(hD.y, b0, acc[3][0]);
                acc[3][1] = fma2(hD.y, b1, acc[3][1]);
                acc[3][2] = fma2(hD.y, b2, acc[3][2]);
                acc[3][3] = fma2(hD.y, b3, acc[3][3]);
            }
            __syncwarp();
        }

        // ---- bias+relu, RED scatter, m_sym (dup'd) ----
        #pragma unroll
        for (int es = 0; es < 4; es++) {
            const int e = 2*es + half;
            const int t = half ? tg[2*es+1] : tg[2*es];
            const int s = half ? sr[2*es+1] : sr[2*es];
            float2 a0 = unpack2(acc[es][0]);
            float2 a1 = unpack2(acc[es][1]);
            float2 a2 = unpack2(acc[es][2]);
            float2 a3 = unpack2(acc[es][3]);
            float f0 = fmaxf(a0.x + b2p.x, 0.f), g0 = fmaxf(a0.y + b2p.x, 0.f);
            float f1 = fmaxf(a1.x + b2p.y, 0.f), g1 = fmaxf(a1.y + b2p.y, 0.f);
            float f2 = fmaxf(a2.x + b2p.z, 0.f), g2 = fmaxf(a2.y + b2p.z, 0.f);
            float f3 = fmaxf(a3.x + b2p.w, 0.f), g3 = fmaxf(a3.y + b2p.w, 0.f);
            red_add_v2(g_aggr + (size_t)t*DMSG + 4*l16,     f0, f1);
            red_add_v2(g_aggr + (size_t)t*DMSG + 4*l16 + 2, f2, f3);
            red_add_v2(g_aggr + (size_t)s*DMSG + 4*l16,     g0, g1);
            red_add_v2(g_aggr + (size_t)s*DMSG + 4*l16 + 2, g2, g3);
            float s0 = f0+g0, s1 = f1+g1, s2 = f2+g2, s3 = f3+g3;
            float4 svA; svA.x = s0; svA.y = s0; svA.z = s1; svA.w = s1;
            float4 svB; svB.x = s2; svB.y = s2; svB.z = s3; svB.w = s3;
            *(float4*)(ms_w + e*(2*DMSG) + 8*l16)     = svA;
            *(float4*)(ms_w + e*(2*DMSG) + 8*l16 + 4) = svB;
        }
        if (lane < 2*EK_B) {
            int e = lane >> 1;
            int node = (lane & 1) ? sr[e] : tg[e];
            red_add_f32(g_cnt + node, 1.f);
        }
        __syncwarp();

        // ---- tension MLP: all 8 edges in one d-loop, weights loaded once ----
        ull tac[4];
        tac[0] = 0ULL; tac[1] = 0ULL; tac[2] = 0ULL; tac[3] = 0ULL;
        #pragma unroll 4
        for (int d = 0; d < DMSG; d += 2) {
            ull w0 = *(const ull*)(sm + OFF_WT1 + d*HTEN     + 2*l16);
            ull w1 = *(const ull*)(sm + OFF_WT1 + (d+1)*HTEN + 2*l16);
            #pragma unroll
            for (int p = 0; p < 4; p++) {
                const float* msp = ms_w + (2*p + half)*(2*DMSG);
                ulonglong2 mv = *(const ulonglong2*)(msp + 2*d);
                tac[p] = fma2(mv.x, w0, tac[p]);
                tac[p] = fma2(mv.y, w1, tac[p]);
            }
        }
        #pragma unroll
        for (int p = 0; p < 4; p++) {
            float2 ac = unpack2(tac[p]);
            float h0 = fmaxf(ac.x + bt1p.x, 0.f);
            float h1 = fmaxf(ac.y + bt1p.y, 0.f);
            float c  = h0*wt2p.x + h1*wt2p.y;
            #pragma unroll
            for (int off = 8; off > 0; off >>= 1)
                c += __shfl_xor_sync(0xffffffffu, c, off);
            if (l16 == 0) e_out[base + 2*p + half] = c + bt2v;
        }
        __syncwarp();
    }
}

// ---------------- node kernel ----------------
#define NK_NW 16
#define NOFF_WU1 0
#define NOFF_WU2 (NOFF_WU1 + (DNODE+DMSG)*HUPD)
#define NOFF_BU1 (NOFF_WU2 + HUPD*DOUT)
#define NOFF_BU2 (NOFF_BU1 + HUPD)
#define NOFF_IN  (NOFF_BU2 + DOUT)
#define NOFF_H   (NOFF_IN + NK_NW*(DNODE+DMSG))
#define NK_SMEM_FLOATS (NOFF_H + NK_NW*HUPD)

__global__ void __launch_bounds__(NK_NW * 32, 1)
node_kernel(const float* __restrict__ x,
            const float* __restrict__ Wu1, const float* __restrict__ bu1,
            const float* __restrict__ Wu2, const float* __restrict__ bu2,
            float* __restrict__ x_out)
{
    extern __shared__ float sm[];
    for (int i = threadIdx.x; i < (DNODE+DMSG)*HUPD; i += blockDim.x) sm[NOFF_WU1+i] = Wu1[i];
    for (int i = threadIdx.x; i < HUPD*DOUT;          i += blockDim.x) sm[NOFF_WU2+i] = Wu2[i];
    for (int i = threadIdx.x; i < HUPD; i += blockDim.x) sm[NOFF_BU1+i] = bu1[i];
    for (int i = threadIdx.x; i < DOUT; i += blockDim.x) sm[NOFF_BU2+i] = bu2[i];
    __syncthreads();

    const int lane = threadIdx.x & 31;
    const int warp = threadIdx.x >> 5;
    float* in_sh = sm + NOFF_IN + warp * (DNODE + DMSG);
    float* h_sh  = sm + NOFF_H  + warp * HUPD;
    const int gw     = blockIdx.x * NK_NW + warp;
    const int nwarps = gridDim.x * NK_NW;

    for (int n = gw; n < NN; n += nwarps) {
        float inv = 1.f / fmaxf(g_cnt[n], 1.f);
        in_sh[lane]      = x[(size_t)n*DNODE + lane];
        in_sh[32 + lane] = x[(size_t)n*DNODE + 32 + lane];
        in_sh[64 + lane] = g_aggr[(size_t)n*DMSG + lane] * inv;
        in_sh[96 + lane] = g_aggr[(size_t)n*DMSG + 32 + lane] * inv;
        __syncwarp();

        float a0 = 0.f, a1 = 0.f;
        #pragma unroll 8
        for (int i = 0; i < DNODE + DMSG; i += 2) {
            float2 v = *(const float2*)&in_sh[i];
            a0 = fmaf(v.x, sm[NOFF_WU1 + i*HUPD         + lane], a0);
            a0 = fmaf(v.y, sm[NOFF_WU1 + (i+1)*HUPD     + lane], a0);
            a1 = fmaf(v.x, sm[NOFF_WU1 + i*HUPD    + 32 + lane], a1);
            a1 = fmaf(v.y, sm[NOFF_WU1 + (i+1)*HUPD + 32 + lane], a1);
        }
        h_sh[lane]      = fmaxf(a0 + sm[NOFF_BU1 + lane], 0.f);
        h_sh[32 + lane] = fmaxf(a1 + sm[NOFF_BU1 + 32 + lane], 0.f);
        __syncwarp();

        float o = 0.f;
        #pragma unroll 8
        for (int j = 0; j < HUPD; j += 2) {
            float2 v = *(const float2*)&h_sh[j];
            o = fmaf(v.x, sm[NOFF_WU2 + j*DOUT     + lane], o);
            o = fmaf(v.y, sm[NOFF_WU2 + (j+1)*DOUT + lane], o);
        }
        x_out[(size_t)n*DOUT + lane] = o + sm[NOFF_BU2 + lane];
        __syncwarp();
    }
}

// ---------------- launch ----------------
extern "C" void kernel_launch(void* const* d_in, const int* in_sizes, int n_in,
                              void* d_out, int out_size)
{
    (void)in_sizes; (void)n_in; (void)out_size;
    const float* x   = (const float*)d_in[0];
    const void*  ei  =               d_in[1];
    const float* ea  = (const float*)d_in[2];
    const float* Wm1 = (const float*)d_in[3];
    const float* bm1 = (const float*)d_in[4];
    const float* Wm2 = (const float*)d_in[5];
    const float* bm2 = (const float*)d_in[6];
    const float* Wu1 = (const float*)d_in[7];
    const float* bu1 = (const float*)d_in[8];
    const float* Wu2 = (const float*)d_in[9];
    const float* bu2 = (const float*)d_in[10];
    const float* Wt1 = (const float*)d_in[11];
    const float* bt1 = (const float*)d_in[12];
    const float* Wt2 = (const float*)d_in[13];
    const float* bt2 = (const float*)d_in[14];

    float* x_out = (float*)d_out;
    float* e_out = x_out + (size_t)NN * DOUT;

    int nsm = 148;
    cudaDeviceGetAttribute(&nsm, cudaDevAttrMultiProcessorCount, 0);

    cudaFuncSetAttribute(precompute_y_kernel, cudaFuncAttributeMaxDynamicSharedMemorySize,
                         PY_SMEM_FLOATS * (int)sizeof(float));
    cudaFuncSetAttribute(edge_kernel, cudaFuncAttributeMaxDynamicSharedMemorySize,
                         EK_SMEM_FLOATS * (int)sizeof(float));
    cudaFuncSetAttribute(node_kernel, cudaFuncAttributeMaxDynamicSharedMemorySize,
                         NK_SMEM_FLOATS * (int)sizeof(float));

    init_kernel<<<1024, 256>>>(ei);
    precompute_y_kernel<<<nsm, PY_NW * 32, PY_SMEM_FLOATS * sizeof(float)>>>(x, Wm1);
    edge_kernel<<<nsm, EK_NW * 32, EK_SMEM_FLOATS * sizeof(float)>>>(
        ei, ea, Wm1, bm1, Wm2, bm2, Wt1, bt1, Wt2, bt2, e_out);
    node_kernel<<<nsm, NK_NW * 32, NK_SMEM_FLOATS * sizeof(float)>>>(
        x, Wu1, bu1, Wu2, bu2, x_out);
}

// round 14
// speedup vs baseline: 1.5547x; 1.0649x over previous
#include <cuda_runtime.h>
#include <cstdint>
#include <cstddef>

// ---------------- problem constants ----------------
#define NN     50000
#define NE     500000
#define DNODE  64
#define DEDGE  8
#define DIN    72
#define HMSG   128
#define DMSG   64
#define HUPD   64
#define DOUT   32
#define HTEN   32

typedef unsigned long long ull;

// ---------------- device scratch ----------------
__device__ float g_aggr[(size_t)NN * DMSG];
__device__ float g_cnt[NN];
__device__ float g_y[(size_t)NN * HMSG];     // y = x @ Wm1[0:64]  (25.6 MB)
__device__ int   g_idx64;

// ---------------- packed f32x2 helpers ----------------
__device__ __forceinline__ ull fma2(ull a, ull b, ull c) {
    ull d; asm("fma.rn.f32x2 %0, %1, %2, %3;" : "=l"(d) : "l"(a), "l"(b), "l"(c));
    return d;
}
__device__ __forceinline__ ull dup2(float x) {
    ull d; asm("mov.b64 %0, {%1, %1};" : "=l"(d) : "f"(x)); return d;
}
__device__ __forceinline__ float2 unpack2(ull v) {
    float2 r; asm("mov.b64 {%0, %1}, %2;" : "=f"(r.x), "=f"(r.y) : "l"(v)); return r;
}
__device__ __forceinline__ void red_add_v2(float* addr, float a, float b) {
    asm volatile("red.global.add.v2.f32 [%0], {%1, %2};"
                 :: "l"(addr), "f"(a), "f"(b) : "memory");
}
__device__ __forceinline__ void red_add_f32(float* addr, float v) {
    asm volatile("red.global.add.f32 [%0], %1;"
                 :: "l"(addr), "f"(v) : "memory");
}

// ---------------- init ----------------
__global__ void init_kernel(const void* __restrict__ ei) {
    size_t tid    = (size_t)blockIdx.x * blockDim.x + threadIdx.x;
    size_t stride = (size_t)gridDim.x * blockDim.x;
    for (size_t i = tid; i < (size_t)NN * DMSG; i += stride) g_aggr[i] = 0.f;
    for (size_t i = tid; i < (size_t)NN; i += stride)        g_cnt[i]  = 0.f;
    if (tid == 0) {
        const unsigned long long* p = (const unsigned long long*)ei;
        int is64 = 1;
        for (int k = 0; k < 64; k++)
            if (p[k] >= (unsigned long long)NN) { is64 = 0; break; }
        g_idx64 = is64;
    }
}

// ---------------- precompute y = x @ Wm1[0:64,:]  ----------------
#define PY_NW 16
#define PYOFF_W 0                              // 64*128 = 8192 fl
#define PYOFF_X (PYOFF_W + DNODE*HMSG)         // dup'd x: 128 fl/warp
#define PY_SMEM_FLOATS (PYOFF_X + PY_NW*2*DNODE)

__global__ void __launch_bounds__(PY_NW * 32, 1)
precompute_y_kernel(const float* __restrict__ x, const float* __restrict__ Wm1)
{
    extern __shared__ float sm[];
    for (int i = threadIdx.x; i < DNODE*HMSG; i += blockDim.x) sm[PYOFF_W+i] = Wm1[i];
    __syncthreads();

    const int lane = threadIdx.x & 31;
    const int warp = threadIdx.x >> 5;
    float* xs_w = sm + PYOFF_X + warp * (2*DNODE);

    const int gw     = blockIdx.x * PY_NW + warp;
    const int nwarps = gridDim.x * PY_NW;

    for (int n = gw; n < NN; n += nwarps) {
        const float2 xv = *(const float2*)(x + (size_t)n*DNODE + 2*lane);
        float4 d; d.x = xv.x; d.y = xv.x; d.z = xv.y; d.w = xv.y;
        *(float4*)(xs_w + 4*lane) = d;
        __syncwarp();

        ull a0 = 0ULL, a1 = 0ULL;
        #pragma unroll 8
        for (int i = 0; i < DNODE; i++) {
            ulonglong2 w2 = *(const ulonglong2*)(sm + PYOFF_W + i*HMSG + 4*lane);
            ull vv = *(const ull*)(xs_w + 2*i);
            a0 = fma2(vv, w2.x, a0);
            a1 = fma2(vv, w2.y, a1);
        }
        ulonglong2 o; o.x = a0; o.y = a1;
        *(ulonglong2*)(g_y + (size_t)n*HMSG + 4*lane) = o;
        __syncwarp();
    }
}

// ---------------- edge kernel ----------------
#define EK_NW 16
#define EK_B  8
#define HCHUNK 64

#define OFF_WM1 0
#define OFF_WM2 (OFF_WM1 + DIN*HMSG)            // 9216
#define OFF_WT1 (OFF_WM2 + HMSG*DMSG)           // 17408 (d-pair transposed)
#define OFF_BM1 (OFF_WT1 + DMSG*HTEN)           // 19456
#define OFF_BM2 (OFF_BM1 + HMSG)                // 19584
#define OFF_BT1 (OFF_BM2 + DMSG)                // 19648
#define OFF_WT2 (OFF_BT1 + HTEN)                // 19680
#define OFF_BT2 (OFF_WT2 + HTEN)                // 19712
#define OFF_EA  (OFF_BT2 + 4)                   // 19716, 16B aligned
#define OFF_MS  (OFF_EA + EK_NW*EK_B*2*DEDGE)   // +16*128  = 21764
#define OFF_H   (OFF_MS + EK_NW*EK_B*2*DMSG)    // +16*1024 = 38148
#define EK_SMEM_FLOATS (OFF_H + EK_NW*EK_B*2*HCHUNK) // +16*1024 = 54532 fl (218KB)

__global__ void __launch_bounds__(EK_NW * 32, 1)
edge_kernel(const void* __restrict__ ei,
            const float* __restrict__ ea,
            const float* __restrict__ Wm1, const float* __restrict__ bm1,
            const float* __restrict__ Wm2, const float* __restrict__ bm2,
            const float* __restrict__ Wt1, const float* __restrict__ bt1,
            const float* __restrict__ Wt2, const float* __restrict__ bt2,
            float* __restrict__ e_out)
{
    extern __shared__ float sm[];
    for (int i = threadIdx.x; i < DIN*HMSG;  i += blockDim.x) sm[OFF_WM1+i] = Wm1[i];
    for (int i = threadIdx.x; i < HMSG*DMSG; i += blockDim.x) sm[OFF_WM2+i] = Wm2[i];
    // Wt1 transposed into d-pair interleave: for d-pair s, out-pair k:
    // {W[2s][2k], W[2s][2k+1], W[2s+1][2k], W[2s+1][2k+1]} contiguous.
    for (int idx = threadIdx.x; idx < 32*16; idx += blockDim.x) {
        int s = idx >> 4, k = idx & 15;
        float* dst = sm + OFF_WT1 + s*64 + 4*k;
        dst[0] = Wt1[(2*s)*HTEN   + 2*k];
        dst[1] = Wt1[(2*s)*HTEN   + 2*k+1];
        dst[2] = Wt1[(2*s+1)*HTEN + 2*k];
        dst[3] = Wt1[(2*s+1)*HTEN + 2*k+1];
    }
    for (int i = threadIdx.x; i < HMSG; i += blockDim.x) sm[OFF_BM1+i] = bm1[i];
    for (int i = threadIdx.x; i < DMSG; i += blockDim.x) sm[OFF_BM2+i] = bm2[i];
    for (int i = threadIdx.x; i < HTEN; i += blockDim.x) {
        sm[OFF_BT1+i] = bt1[i];
        sm[OFF_WT2+i] = Wt2[i];
    }
    if (threadIdx.x == 0) sm[OFF_BT2] = bt2[0];
    __syncthreads();

    const int lane = threadIdx.x & 31;
    const int warp = threadIdx.x >> 5;
    const int half = lane >> 4;
    const int l16  = lane & 15;

    float* ea_w = sm + OFF_EA + warp * (EK_B * 2 * DEDGE);
    float* ms_w = sm + OFF_MS + warp * (EK_B * 2 * DMSG);
    float* h_w  = sm + OFF_H  + warp * (EK_B * 2 * HCHUNK);

    const float4 b1p  = *(const float4*)(sm + OFF_BM1 + 4*lane);
    const float4 b2p  = *(const float4*)(sm + OFF_BM2 + 4*l16);
    const float2 bt1p = *(const float2*)(sm + OFF_BT1 + 2*l16);
    const float2 wt2p = *(const float2*)(sm + OFF_WT2 + 2*l16);
    const float  bt2v = sm[OFF_BT2];
    const ull    NEG1 = dup2(-1.0f);

    const bool idx64 = (g_idx64 != 0);
    const long long* ei64 = (const long long*)ei;
    const int*       ei32 = (const int*)ei;

    const int gw     = blockIdx.x * EK_NW + warp;
    const int nwarps = gridDim.x * EK_NW;

    for (int base = gw * EK_B; base < NE; base += nwarps * EK_B) {
        int sr[EK_B], tg[EK_B];
        #pragma unroll
        for (int e = 0; e < EK_B; e++) {
            int id = base + e;
            if (idx64) { sr[e] = (int)ei64[id]; tg[e] = (int)ei64[NE + id]; }
            else       { sr[e] = ei32[id];      tg[e] = ei32[NE + id]; }
        }

        // ---- stage duplicated edge attrs ----
        {
            int e = lane >> 2, l4 = lane & 3;
            float2 ev = *(const float2*)(ea + (size_t)(base + e)*DEDGE + 2*l4);
            float4 d; d.x = ev.x; d.y = ev.x; d.z = ev.y; d.w = ev.y;
            *(float4*)(ea_w + e*(2*DEDGE) + 4*l4) = d;
        }
        __syncwarp();

        // ---- layer 1 via precomputed y: z = y[t] - y[s] + Wm1[64:72]^T ea ----
        ull z[EK_B][2];
        #pragma unroll
        for (int e = 0; e < EK_B; e++) {
            ulonglong2 yt = *(const ulonglong2*)(g_y + (size_t)tg[e]*HMSG + 4*lane);
            ulonglong2 ys = *(const ulonglong2*)(g_y + (size_t)sr[e]*HMSG + 4*lane);
            z[e][0] = fma2(ys.x, NEG1, yt.x);
            z[e][1] = fma2(ys.y, NEG1, yt.y);
        }
        #pragma unroll
        for (int i = 0; i < DEDGE; i++) {
            ulonglong2 w2 = *(const ulonglong2*)(sm + OFF_WM1 + (DNODE+i)*HMSG + 4*lane);
            #pragma unroll
            for (int e = 0; e < EK_B; e++) {
                ull vv = *(const ull*)(ea_w + e*(2*DEDGE) + 2*i);
                z[e][0] = fma2(vv, w2.x, z[e][0]);
                z[e][1] = fma2(vv, w2.y, z[e][1]);
            }
        }

        // ---- layer 2 in two 64-j chunks sharing one small h buffer ----
        ull acc[4][4];
        #pragma unroll
        for (int es = 0; es < 4; es++)
            #pragma unroll
            for (int k = 0; k < 4; k++) acc[es][k] = 0ULL;

        const float* hp0 = h_w + (0 + half)*(2*HCHUNK);
        const float* hp1 = h_w + (2 + half)*(2*HCHUNK);
        const float* hp2 = h_w + (4 + half)*(2*HCHUNK);
        const float* hp3 = h_w + (6 + half)*(2*HCHUNK);

        #pragma unroll
        for (int c = 0; c < 2; c++) {
            if (half == c) {
                #pragma unroll
                for (int e = 0; e < EK_B; e++) {
                    float2 za = unpack2(z[e][0]);
                    float2 zb = unpack2(z[e][1]);
                    float4 h0, h1;
                    h0.x = fmaxf(za.x + b1p.x, 0.f); h0.y = fmaxf(b1p.x - za.x, 0.f);
                    h0.z = fmaxf(za.y + b1p.y, 0.f); h0.w = fmaxf(b1p.y - za.y, 0.f);
                    h1.x = fmaxf(zb.x + b1p.z, 0.f); h1.y = fmaxf(b1p.z - zb.x, 0.f);
                    h1.z = fmaxf(zb.y + b1p.w, 0.f); h1.w = fmaxf(b1p.w - zb.y, 0.f);
                    *(float4*)(h_w + e*(2*HCHUNK) + 8*l16)     = h0;
                    *(float4*)(h_w + e*(2*HCHUNK) + 8*l16 + 4) = h1;
                }
            }
            __syncwarp();

            #pragma unroll 2
            for (int jj = 0; jj < HCHUNK; jj += 2) {
                const float* wrow = sm + OFF_WM2 + (c*HCHUNK + jj)*DMSG + 4*l16;
                ulonglong2 wj0 = *(const ulonglong2*)wrow;
                ulonglong2 wj1 = *(const ulonglong2*)(wrow + DMSG);
                float2 w0lo = unpack2(wj0.x), w0hi = unpack2(wj0.y);
                float2 w1lo = unpack2(wj1.x), w1hi = unpack2(wj1.y);
                ull a0 = dup2(w0lo.x), a1 = dup2(w0lo.y), a2 = dup2(w0hi.x), a3 = dup2(w0hi.y);
                ull b0 = dup2(w1lo.x), b1 = dup2(w1lo.y), b2 = dup2(w1hi.x), b3 = dup2(w1hi.y);
                ulonglong2 hA = *(const ulonglong2*)(hp0 + 2*jj);
                ulonglong2 hB = *(const ulonglong2*)(hp1 + 2*jj);
                ulonglong2 hC = *(const ulonglong2*)(hp2 + 2*jj);
                ulonglong2 hD = *(const ulonglong2*)(hp3 + 2*jj);
                acc[0][0] = fma2(hA.x, a0, acc[0][0]);
                acc[0][1] = fma2(hA.x, a1, acc[0][1]);
                acc[0][2] = fma2(hA.x, a2, acc[0][2]);
                acc[0][3] = fma2(hA.x, a3, acc[0][3]);
                acc[1][0] = fma2(hB.x, a0, acc[1][0]);
                acc[1][1] = fma2(hB.x, a1, acc[1][1]);
                acc[1][2] = fma2(hB.x, a2, acc[1][2]);
                acc[1][3] = fma2(hB.x, a3, acc[1][3]);
                acc[2][0] = fma2(hC.x, a0, acc[2][0]);
                acc[2][1] = fma2(hC.x, a1, acc[2][1]);
                acc[2][2] = fma2(hC.x, a2, acc[2][2]);
                acc[2][3] = fma2(hC.x, a3, acc[2][3]);
                acc[3][0] = fma2(hD.x, a0, acc[3][0]);
                acc[3][1] = fma2(hD.x, a1, acc[3][1]);
                acc[3][2] = fma2(hD.x, a2, acc[3][2]);
                acc[3][3] = fma2(hD.x, a3, acc[3][3]);
                acc[0][0] = fma2(hA.y, b0, acc[0][0]);
                acc[0][1] = fma2(hA.y, b1, acc[0][1]);
                acc[0][2] = fma2(hA.y, b2, acc[0][2]);
                acc[0][3] = fma2(hA.y, b3, acc[0][3]);
                acc[1][0] = fma2(hB.y, b0, acc[1][0]);
                acc[1][1] = fma2(hB.y, b1, acc[1][1]);
                acc[1][2] = fma2(hB.y, b2, acc[1][2]);
                acc[1][3] = fma2(hB.y, b3, acc[1][3]);
                acc[2][0] = fma2(hC.y, b0, acc[2][0]);
                acc[2][1] = fma2(hC.y, b1, acc[2][1]);
                acc[2][2] = fma2(hC.y, b2, acc[2][2]);
                acc[2][3] = fma2(hC.y, b3, acc[2][3]);
                acc[3][0] = fma2(hD.y, b0, acc[3][0]);
                acc[3][1] = fma2(hD.y, b1, acc[3][1]);
                acc[3][2] = fma2(hD.y, b2, acc[3][2]);
                acc[3][3] = fma2(hD.y, b3, acc[3][3]);
            }
            __syncwarp();
        }

        // ---- bias+relu, RED scatter, m_sym (dup'd) ----
        #pragma unroll
        for (int es = 0; es < 4; es++) {
            const int e = 2*es + half;
            const int t = half ? tg[2*es+1] : tg[2*es];
            const int s = half ? sr[2*es+1] : sr[2*es];
            float2 a0 = unpack2(acc[es][0]);
            float2 a1 = unpack2(acc[es][1]);
            float2 a2 = unpack2(acc[es][2]);
            float2 a3 = unpack2(acc[es][3]);
            float f0 = fmaxf(a0.x + b2p.x, 0.f), g0 = fmaxf(a0.y + b2p.x, 0.f);
            float f1 = fmaxf(a1.x + b2p.y, 0.f), g1 = fmaxf(a1.y + b2p.y, 0.f);
            float f2 = fmaxf(a2.x + b2p.z, 0.f), g2 = fmaxf(a2.y + b2p.z, 0.f);
            float f3 = fmaxf(a3.x + b2p.w, 0.f), g3 = fmaxf(a3.y + b2p.w, 0.f);
            red_add_v2(g_aggr + (size_t)t*DMSG + 4*l16,     f0, f1);
            red_add_v2(g_aggr + (size_t)t*DMSG + 4*l16 + 2, f2, f3);
            red_add_v2(g_aggr + (size_t)s*DMSG + 4*l16,     g0, g1);
            red_add_v2(g_aggr + (size_t)s*DMSG + 4*l16 + 2, g2, g3);
            float s0 = f0+g0, s1 = f1+g1, s2 = f2+g2, s3 = f3+g3;
            float4 svA; svA.x = s0; svA.y = s0; svA.z = s1; svA.w = s1;
            float4 svB; svB.x = s2; svB.y = s2; svB.z = s3; svB.w = s3;
            *(float4*)(ms_w + e*(2*DMSG) + 8*l16)     = svA;
            *(float4*)(ms_w + e*(2*DMSG) + 8*l16 + 4) = svB;
        }
        if (lane < 2*EK_B) {
            int e = lane >> 1;
            int node = (lane & 1) ? sr[e] : tg[e];
            red_add_f32(g_cnt + node, 1.f);
        }
        __syncwarp();

        // ---- tension MLP: paired-transposed weights, one LDS.128 per 2d ----
        ull tac[4];
        tac[0] = 0ULL; tac[1] = 0ULL; tac[2] = 0ULL; tac[3] = 0ULL;
        #pragma unroll 4
        for (int s = 0; s < 32; s++) {
            ulonglong2 w = *(const ulonglong2*)(sm + OFF_WT1 + s*64 + 4*l16);
            #pragma unroll
            for (int p = 0; p < 4; p++) {
                const float* msp = ms_w + (2*p + half)*(2*DMSG);
                ulonglong2 mv = *(const ulonglong2*)(msp + 4*s); // {s_2s,s_2s,s_2s+1,s_2s+1}
                tac[p] = fma2(mv.x, w.x, tac[p]);
                tac[p] = fma2(mv.y, w.y, tac[p]);
            }
        }
        #pragma unroll
        for (int p = 0; p < 4; p++) {
            float2 ac = unpack2(tac[p]);
            float h0 = fmaxf(ac.x + bt1p.x, 0.f);
            float h1 = fmaxf(ac.y + bt1p.y, 0.f);
            float c  = h0*wt2p.x + h1*wt2p.y;
            #pragma unroll
            for (int off = 8; off > 0; off >>= 1)
                c += __shfl_xor_sync(0xffffffffu, c, off);
            if (l16 == 0) e_out[base + 2*p + half] = c + bt2v;
        }
        __syncwarp();
    }
}

// ---------------- node kernel v2: 4 nodes/warp, paired-transposed weights ----
#define NK_NW 16
#define NB    4
#define NOFF_W1T 0                                   // 64 steps * 128 = 8192 fl
#define NOFF_W2T (NOFF_W1T + 8192)                   // 32 steps * 64 = 2048 fl
#define NOFF_BU1 (NOFF_W2T + 2048)                   // 64
#define NOFF_BU2 (NOFF_BU1 + HUPD)                   // 32
#define NOFF_IN  (NOFF_BU2 + DOUT)                   // per warp: NB*128
#define NOFF_H   (NOFF_IN + NK_NW*NB*(DNODE+DMSG))   // per warp: NB*64
#define NK_SMEM_FLOATS (NOFF_H + NK_NW*NB*HUPD)      // 22624 fl = 90.5 KB

__global__ void __launch_bounds__(NK_NW * 32, 1)
node_kernel(const float* __restrict__ x,
            const float* __restrict__ Wu1, const float* __restrict__ bu1,
            const float* __restrict__ Wu2, const float* __restrict__ bu2,
            float* __restrict__ x_out)
{
    extern __shared__ float sm[];
    // Wu1 transposed into i-pair interleave: w1t[s*128 + 2k .. 2k+1] =
    // {Wu1[2s][k], Wu1[2s+1][k]}
    for (int idx = threadIdx.x; idx < 64*64; idx += blockDim.x) {
        int s = idx >> 6, k = idx & 63;
        sm[NOFF_W1T + s*128 + 2*k]     = Wu1[(2*s)*HUPD   + k];
        sm[NOFF_W1T + s*128 + 2*k + 1] = Wu1[(2*s+1)*HUPD + k];
    }
    for (int idx = threadIdx.x; idx < 32*32; idx += blockDim.x) {
        int s = idx >> 5, o = idx & 31;
        sm[NOFF_W2T + s*64 + 2*o]     = Wu2[(2*s)*DOUT   + o];
        sm[NOFF_W2T + s*64 + 2*o + 1] = Wu2[(2*s+1)*DOUT + o];
    }
    for (int i = threadIdx.x; i < HUPD; i += blockDim.x) sm[NOFF_BU1+i] = bu1[i];
    for (int i = threadIdx.x; i < DOUT; i += blockDim.x) sm[NOFF_BU2+i] = bu2[i];
    __syncthreads();

    const int lane = threadIdx.x & 31;
    const int warp = threadIdx.x >> 5;
    float* in_w = sm + NOFF_IN + warp * (NB * 128);
    float* h_w  = sm + NOFF_H  + warp * (NB * HUPD);

    const float2 b1 = *(const float2*)(sm + NOFF_BU1 + 2*lane);
    const float  b2 = sm[NOFF_BU2 + lane];

    const int gw     = blockIdx.x * NK_NW + warp;
    const int nwarps = gridDim.x * NK_NW;

    for (int n0 = gw * NB; n0 < NN; n0 += nwarps * NB) {
        // ---- stage [x | aggr/cnt] (plain layout, pairs read as ull) ----
        #pragma unroll
        for (int e = 0; e < NB; e++) {
            int n = n0 + e; if (n >= NN) n = NN - 1;
            float inv = 1.f / fmaxf(g_cnt[n], 1.f);
            float2 xv = *(const float2*)(x + (size_t)n*DNODE + 2*lane);
            float2 av = *(const float2*)(g_aggr + (size_t)n*DMSG + 2*lane);
            av.x *= inv; av.y *= inv;
            *(float2*)(in_w + e*128 + 2*lane)      = xv;
            *(float2*)(in_w + e*128 + 64 + 2*lane) = av;
        }
        __syncwarp();

        // ---- layer 1: lane owns outputs 2L, 2L+1; acc pairs fold i-even/odd ----
        ull accA[NB], accB[NB];
        #pragma unroll
        for (int e = 0; e < NB; e++) { accA[e] = 0ULL; accB[e] = 0ULL; }

        #pragma unroll 8
        for (int s = 0; s < 64; s++) {
            ulonglong2 w = *(const ulonglong2*)(sm + NOFF_W1T + s*128 + 4*lane);
            #pragma unroll
            for (int e = 0; e < NB; e++) {
                ull vv = *(const ull*)(in_w + e*128 + 2*s);  // {v_2s, v_2s+1}
                accA[e] = fma2(vv, w.x, accA[e]);
                accB[e] = fma2(vv, w.y, accB[e]);
            }
        }
        #pragma unroll
        for (int e = 0; e < NB; e++) {
            float2 a = unpack2(accA[e]);
            float2 b = unpack2(accB[e]);
            float2 h;
            h.x = fmaxf(a.x + a.y + b1.x, 0.f);
            h.y = fmaxf(b.x + b.y + b1.y, 0.f);
            *(float2*)(h_w + e*HUPD + 2*lane) = h;
        }
        __syncwarp();

        // ---- layer 2: lane owns output o = lane ----
        ull acc2[NB];
        #pragma unroll
        for (int e = 0; e < NB; e++) acc2[e] = 0ULL;
        #pragma unroll 8
        for (int s = 0; s < 32; s++) {
            ull w = *(const ull*)(sm + NOFF_W2T + s*64 + 2*lane);
            #pragma unroll
            for (int e = 0; e < NB; e++) {
                ull hv = *(const ull*)(h_w + e*HUPD + 2*s);   // {h_2s, h_2s+1}
                acc2[e] = fma2(hv, w, acc2[e]);
            }
        }
        #pragma unroll
        for (int e = 0; e < NB; e++) {
            int n = n0 + e;
            if (n < NN) {
                float2 a = unpack2(acc2[e]);
                x_out[(size_t)n*DOUT + lane] = a.x + a.y + b2;
            }
        }
        __syncwarp();
    }
}

// ---------------- launch ----------------
extern "C" void kernel_launch(void* const* d_in, const int* in_sizes, int n_in,
                              void* d_out, int out_size)
{
    (void)in_sizes; (void)n_in; (void)out_size;
    const float* x   = (const float*)d_in[0];
    const void*  ei  =               d_in[1];
    const float* ea  = (const float*)d_in[2];
    const float* Wm1 = (const float*)d_in[3];
    const float* bm1 = (const float*)d_in[4];
    const float* Wm2 = (const float*)d_in[5];
    const float* bm2 = (const float*)d_in[6];
    const float* Wu1 = (const float*)d_in[7];
    const float* bu1 = (const float*)d_in[8];
    const float* Wu2 = (const float*)d_in[9];
    const float* bu2 = (const float*)d_in[10];
    const float* Wt1 = (const float*)d_in[11];
    const float* bt1 = (const float*)d_in[12];
    const float* Wt2 = (const float*)d_in[13];
    const float* bt2 = (const float*)d_in[14];

    float* x_out = (float*)d_out;
    float* e_out = x_out + (size_t)NN * DOUT;

    int nsm = 148;
    cudaDeviceGetAttribute(&nsm, cudaDevAttrMultiProcessorCount, 0);

    cudaFuncSetAttribute(precompute_y_kernel, cudaFuncAttributeMaxDynamicSharedMemorySize,
                         PY_SMEM_FLOATS * (int)sizeof(float));
    cudaFuncSetAttribute(edge_kernel, cudaFuncAttributeMaxDynamicSharedMemorySize,
                         EK_SMEM_FLOATS * (int)sizeof(float));
    cudaFuncSetAttribute(node_kernel, cudaFuncAttributeMaxDynamicSharedMemorySize,
                         NK_SMEM_FLOATS * (int)sizeof(float));

    init_kernel<<<1024, 256>>>(ei);
    precompute_y_kernel<<<nsm, PY_NW * 32, PY_SMEM_FLOATS * sizeof(float)>>>(x, Wm1);
    edge_kernel<<<nsm, EK_NW * 32, EK_SMEM_FLOATS * sizeof(float)>>>(
        ei, ea, Wm1, bm1, Wm2, bm2, Wt1, bt1, Wt2, bt2, e_out);
    node_kernel<<<2*nsm, NK_NW * 32, NK_SMEM_FLOATS * sizeof(float)>>>(
        x, Wu1, bu1, Wu2, bu2, x_out);
}